// round 14
// baseline (speedup 1.0000x reference)
#include <cuda_runtime.h>
#include <cuda_bf16.h>
#include <math.h>
#include <stdint.h>

#define SS    16
#define BB    128
#define FEATD 2048
#define HANDD 63
#define HH    1024
#define CC    1000
#define HPAD  128

// ---------------------------------------------------------------------------
// Scratch layout
// ---------------------------------------------------------------------------
#define NB_FEATS (SS*BB*FEATD)
#define NB_X     (SS*BB*2*HH)
#define NB_HANDS (SS*BB*HPAD)
#define NB_FC1   (HH*FEATD)
#define NB_FCHW  (HH*HPAD)
#define NB_RWIH  (4*HH*2*HH)
#define NB_RWHH  (4*HH*HH)
#define NB_CLS   (1024*HH)
#define NB_H     (BB*HH)

#define OFF_FEATSH  0
#define OFF_FEATSM  (OFF_FEATSH + NB_FEATS/2)
#define OFF_XH      (OFF_FEATSM + NB_FEATS/2)
#define OFF_XM      (OFF_XH     + NB_X/2)
#define OFF_GATESX  (OFF_XM     + NB_X/2)
#define OFF_GATESXU (OFF_GATESX + SS*BB*4*HH)
#define OFF_H0H     (OFF_GATESXU+ BB*4*HH)
#define OFF_H0M     (OFF_H0H    + NB_H/2)
#define OFF_H1H     (OFF_H0M    + NB_H/2)
#define OFF_H1M     (OFF_H1H    + NB_H/2)
#define OFF_HANDSH  (OFF_H1M    + NB_H/2)
#define OFF_HANDSM  (OFF_HANDSH + NB_HANDS/2)
#define OFF_FC1H    (OFF_HANDSM + NB_HANDS/2)
#define OFF_FC1M    (OFF_FC1H   + NB_FC1/2)
#define OFF_FCHWH   (OFF_FC1M   + NB_FC1/2)
#define OFF_FCHWM   (OFF_FCHWH  + NB_FCHW/2)
#define OFF_RWIHH   (OFF_FCHWM  + NB_FCHW/2)
#define OFF_RWIHM   (OFF_RWIHH  + NB_RWIH/2)
#define OFF_RWHHH   (OFF_RWIHM  + NB_RWIH/2)
#define OFF_RWHHM   (OFF_RWHHH  + NB_RWHH/2)
#define OFF_UWIHH   (OFF_RWHHM  + NB_RWHH/2)
#define OFF_UWIHM   (OFF_UWIHH  + NB_RWIH/2)
#define OFF_UWHHH   (OFF_UWIHM  + NB_RWIH/2)
#define OFF_UWHHM   (OFF_UWHHH  + NB_RWHH/2)
#define OFF_CLSH    (OFF_UWHHM  + NB_RWHH/2)
#define OFF_CLSM    (OFF_CLSH   + NB_CLS/2)
#define OFF_LOSSROW (OFF_CLSM   + NB_CLS/2)
#define SCRATCH_TOT (OFF_LOSSROW + BB)

__device__ __align__(16) float g_scratch[SCRATCH_TOT];

// tree grid-barrier state (monotone counters; snapshot at entry -> replay-safe)
__device__ unsigned int g_grp[8];
__device__ unsigned int g_root  = 0;
__device__ unsigned int g_phase = 0;

typedef __nv_bfloat16 bf16;

// ---------------------------------------------------------------------------
// helpers
// ---------------------------------------------------------------------------
__device__ __forceinline__ void split_bf(float v, bf16& h, bf16& m)
{
    h = __float2bfloat16_rn(v);
    m = __float2bfloat16_rn(v - __bfloat162float(h));
}

#define MMA_BF16(d, a, b)                                                     \
    asm volatile(                                                             \
        "mma.sync.aligned.m16n8k16.row.col.f32.bf16.bf16.f32 "                \
        "{%0,%1,%2,%3},{%4,%5,%6,%7},{%8,%9},{%0,%1,%2,%3};"                  \
        : "+f"(d[0]), "+f"(d[1]), "+f"(d[2]), "+f"(d[3])                      \
        : "r"(a[0]), "r"(a[1]), "r"(a[2]), "r"(a[3]), "r"(b[0]), "r"(b[1]))

__device__ __forceinline__ void ldsm4(uint32_t& r0, uint32_t& r1,
                                      uint32_t& r2, uint32_t& r3, uint32_t addr)
{
    asm volatile("ldmatrix.sync.aligned.m8n8.x4.shared.b16 {%0,%1,%2,%3}, [%4];"
                 : "=r"(r0), "=r"(r1), "=r"(r2), "=r"(r3) : "r"(addr));
}
__device__ __forceinline__ void ldsm2(uint32_t& r0, uint32_t& r1, uint32_t addr)
{
    asm volatile("ldmatrix.sync.aligned.m8n8.x2.shared.b16 {%0,%1}, [%2];"
                 : "=r"(r0), "=r"(r1) : "r"(addr));
}

__device__ __forceinline__ void cp16(uint32_t dst, const void* src)
{
    asm volatile("cp.async.cg.shared.global [%0], [%1], 16;" :: "r"(dst), "l"(src));
}
__device__ __forceinline__ void cp_commit() { asm volatile("cp.async.commit_group;"); }
__device__ __forceinline__ void cp_wait()   { asm volatile("cp.async.wait_group 0;"); }
__device__ __forceinline__ void cp_wait1()  { asm volatile("cp.async.wait_group 1;"); }

__device__ __forceinline__ void bar_pair(int id)
{
    asm volatile("bar.sync %0, 64;" :: "r"(id) : "memory");
}

__device__ __forceinline__ unsigned int atom_add_acqrel(unsigned int* p, unsigned int v)
{
    unsigned int old;
    asm volatile("atom.acq_rel.gpu.global.add.u32 %0, [%1], %2;"
                 : "=r"(old) : "l"(p), "r"(v) : "memory");
    return old;
}
__device__ __forceinline__ unsigned int ld_acquire(unsigned int* p)
{
    unsigned int v;
    asm volatile("ld.acquire.gpu.global.u32 %0, [%1];" : "=r"(v) : "l"(p) : "memory");
    return v;
}

// ---------------------------------------------------------------------------
// bf16x2-split GEMM (3 products): C = A*W^T (+bias)  [proven, unchanged]
// ---------------------------------------------------------------------------
template<int PERMBIAS, int SPLITOUT>
__global__ void __launch_bounds__(256, 2)
gemm_bf(const bf16* __restrict__ AH, const bf16* __restrict__ AM, int lda,
        const bf16* __restrict__ WH, const bf16* __restrict__ WM, int ldw,
        float* __restrict__ Cf, bf16* __restrict__ CbH, bf16* __restrict__ CbM,
        int ldc, const float* __restrict__ b1, const float* __restrict__ b2,
        int Nstore, int K)
{
    extern __shared__ __align__(16) char smraw[];
    const uint32_t sbase = (uint32_t)__cvta_generic_to_shared(smraw);

    const int tid  = threadIdx.x;
    const int lane = tid & 31;
    const int warp = tid >> 5;
    const int wm   = warp >> 2;
    const int wn   = warp & 3;
    const int row0 = blockIdx.y * 128;
    const int col0 = blockIdx.x * 128;

    float acc[4][4][4];
#pragma unroll
    for (int i = 0; i < 4; i++)
#pragma unroll
        for (int j = 0; j < 4; j++)
#pragma unroll
            for (int q = 0; q < 4; q++) acc[i][j][q] = 0.f;

    const int r  = tid >> 2;
    const int ch = tid & 3;

    auto gload = [&](int buf, int k0) {
        const uint32_t bo = (uint32_t)(buf * 40960);
#pragma unroll
        for (int l = 0; l < 2; l++) {
            int rr = r + l * 64;
            uint32_t so = (uint32_t)(rr * 80 + ch * 16);
            cp16(sbase + bo +         so, &AH[(size_t)(row0 + rr) * lda + k0 + ch * 8]);
            cp16(sbase + bo + 10240 + so, &AM[(size_t)(row0 + rr) * lda + k0 + ch * 8]);
            cp16(sbase + bo + 20480 + so, &WH[(size_t)(col0 + rr) * ldw + k0 + ch * 8]);
            cp16(sbase + bo + 30720 + so, &WM[(size_t)(col0 + rr) * ldw + k0 + ch * 8]);
        }
        cp_commit();
    };

    const int nk = K / 32;
    gload(0, 0);
    cp_wait();
    __syncthreads();

    for (int kt = 0; kt < nk; kt++) {
        const int cur = kt & 1;
        if (kt + 1 < nk) gload(cur ^ 1, (kt + 1) * 32);

        const uint32_t bo  = (uint32_t)(cur * 40960);
        const uint32_t aA0 = sbase + bo;
        const uint32_t aA1 = sbase + bo + 10240;
        const uint32_t aB0 = sbase + bo + 20480;
        const uint32_t aB1 = sbase + bo + 30720;

#pragma unroll
        for (int s = 0; s < 2; s++) {
            uint32_t b0f[4][2], b1f[4][2];
            const uint32_t bOff = (uint32_t)((lane & 7) * 80 + s * 32 + ((lane >> 3) & 1) * 16);
#pragma unroll
            for (int nt = 0; nt < 4; nt++) {
                uint32_t na = (uint32_t)((wn * 32 + nt * 8) * 80);
                ldsm2(b0f[nt][0], b0f[nt][1], aB0 + na + bOff);
                ldsm2(b1f[nt][0], b1f[nt][1], aB1 + na + bOff);
            }
            const uint32_t aOff = (uint32_t)((lane & 15) * 80 + s * 32 + (lane >> 4) * 16);
#pragma unroll
            for (int mt = 0; mt < 4; mt++) {
                uint32_t ma = (uint32_t)((wm * 64 + mt * 16) * 80);
                uint32_t a0[4], a1[4];
                ldsm4(a0[0], a0[1], a0[2], a0[3], aA0 + ma + aOff);
                ldsm4(a1[0], a1[1], a1[2], a1[3], aA1 + ma + aOff);
#pragma unroll
                for (int nt = 0; nt < 4; nt++) {
                    MMA_BF16(acc[mt][nt], a0, b0f[nt]);
                    MMA_BF16(acc[mt][nt], a0, b1f[nt]);
                    MMA_BF16(acc[mt][nt], a1, b0f[nt]);
                }
            }
        }

        if (kt + 1 < nk) { cp_wait(); __syncthreads(); }
    }

#pragma unroll
    for (int mt = 0; mt < 4; mt++)
#pragma unroll
        for (int nt = 0; nt < 4; nt++) {
            int m = row0 + wm * 64 + mt * 16 + (lane >> 2);
            int n = col0 + wn * 32 + nt * 8 + 2 * (lane & 3);
            if (n + 1 >= Nstore) continue;
            float bv0 = 0.f, bv1 = 0.f;
            int bi0 = PERMBIAS ? ((n & 3) * HH + (n >> 2)) : n;
            int bi1 = PERMBIAS ? (((n + 1) & 3) * HH + ((n + 1) >> 2)) : (n + 1);
            if (b1) { bv0 += b1[bi0]; bv1 += b1[bi1]; }
            if (b2) { bv0 += b2[bi0]; bv1 += b2[bi1]; }
            float v00 = acc[mt][nt][0] + bv0, v01 = acc[mt][nt][1] + bv1;
            float v10 = acc[mt][nt][2] + bv0, v11 = acc[mt][nt][3] + bv1;
            if (SPLITOUT) {
                __nv_bfloat162 h0, m0, h1, m1;
                split_bf(v00, h0.x, m0.x); split_bf(v01, h0.y, m0.y);
                split_bf(v10, h1.x, m1.x); split_bf(v11, h1.y, m1.y);
                *reinterpret_cast<__nv_bfloat162*>(&CbH[(size_t)m * ldc + n])       = h0;
                *reinterpret_cast<__nv_bfloat162*>(&CbM[(size_t)m * ldc + n])       = m0;
                *reinterpret_cast<__nv_bfloat162*>(&CbH[(size_t)(m + 8) * ldc + n]) = h1;
                *reinterpret_cast<__nv_bfloat162*>(&CbM[(size_t)(m + 8) * ldc + n]) = m1;
            } else {
                *reinterpret_cast<float2*>(&Cf[(size_t)m * ldc + n])       = make_float2(v00, v01);
                *reinterpret_cast<float2*>(&Cf[(size_t)(m + 8) * ldc + n]) = make_float2(v10, v11);
            }
        }
}

// ---------------------------------------------------------------------------
// Persistent LSTM recurrence — warp-pair decoupled.
// 512 threads = 8 pairs; pair p owns batches [16p,16p+16): its A rows, gsum
// rows, c rows, h-output rows. K-loop and cell use pair-scope named barriers
// (bar.sync id,64); CTA-wide sync only at weight load and the grid barrier.
//
// smem (dyn, 228352 B):
//   0      : per-pair A, 8 x 9216 (2 bufs x (hi 2304 | mid 2304))   = 73728
//            (pair gsum aliases its buf0-hi, 16 rows x 144 B)
//   73728  : W_H  32 rows x 2096 B                                  = 67072
//   140800 : W_M  32 rows x 2096 B                                  = 67072
//   207872 : gx stage 128 rows x 128 B                              = 16384
//   224256 : c 128 x 8 floats                                       = 4096
// ---------------------------------------------------------------------------
#define PSM   228352
#define PAIRA 9216
#define PBUF  4608
#define PMID  2304
#define ASTR  144
#define SW_H  73728
#define SW_M  140800
#define SGX   207872
#define SCC   224256
#define WSTR  2096
#define PTHREADS 512

__global__ void __launch_bounds__(PTHREADS)
lstm_persistent(const bf16* __restrict__ rwhhH, const bf16* __restrict__ rwhhM,
                const bf16* __restrict__ uwhhH, const bf16* __restrict__ uwhhM,
                const float* __restrict__ gatesx,   // [16][128][4096] permuted
                const float* __restrict__ gatesxu,  // [128][4096] permuted
                bf16* __restrict__ h0H, bf16* __restrict__ h0M,
                bf16* __restrict__ h1H, bf16* __restrict__ h1M)
{
    extern __shared__ __align__(16) char smraw[];
    const uint32_t sbase = (uint32_t)__cvta_generic_to_shared(smraw);
    float* c_sm = reinterpret_cast<float*>(smraw + SCC);

    const int tid  = threadIdx.x;
    const int lane = tid & 31;
    const int warp = tid >> 5;          // 0..15
    const int pr   = warp >> 1;         // 0..7 pair (batch group)
    const int wn   = warp & 1;          // 0..1 N-half within pair
    const int tp   = tid & 63;          // thread-in-pair
    const int col0 = blockIdx.x * 32;
    const int grp  = blockIdx.x >> 4;
    const uint32_t pA = sbase + (uint32_t)(pr * PAIRA);

    __shared__ unsigned int s_phase;
    if (tid == 0) s_phase = g_phase;

#pragma unroll
    for (int q = 0; q < 2; q++) c_sm[tid + q * PTHREADS] = 0.f;

    auto load_weights = [&](const bf16* wH, const bf16* wM) {
        for (int i = tid; i < 4096; i += PTHREADS) {
            int row = i >> 7;
            int chk = i & 127;
            uint32_t so = (uint32_t)(row * WSTR + chk * 16);
            cp16(sbase + SW_H + so, &wH[(size_t)(col0 + row) * HH + chk * 8]);
            cp16(sbase + SW_M + so, &wM[(size_t)(col0 + row) * HH + chk * 8]);
        }
        cp_commit();
        cp_wait();
        __syncthreads();
    };
    load_weights(rwhhH, rwhhM);

    for (int step = 0; step < 18; step++) {
        const bf16* hH = (step & 1) ? h1H : h0H;
        const bf16* hM = (step & 1) ? h1M : h0M;
        bf16* oH = (step & 1) ? h0H : h1H;
        bf16* oM = (step & 1) ? h0M : h1M;
        const float* gx = (step < SS) ? gatesx + (size_t)step * BB * 4 * HH
                                      : gatesxu;

        if (step == SS) load_weights(uwhhH, uwhhM);

        // stage this pair's gx rows (16 x 128 B) — group G_gx
        {
#pragma unroll
            for (int l = 0; l < 2; l++) {
                int idx = tp + l * 64;          // 0..127
                int rl  = idx >> 3;             // local row 0..15
                int chk = idx & 7;
                int b   = pr * 16 + rl;
                cp16(sbase + SGX + (uint32_t)(b * 128 + chk * 16),
                     &gx[(size_t)b * (4 * HH) + col0 + chk * 4]);
            }
            cp_commit();
        }

        float acc[2][4];
#pragma unroll
        for (int j = 0; j < 2; j++)
#pragma unroll
            for (int q = 0; q < 4; q++) acc[j][q] = 0.f;

        float* gsum = reinterpret_cast<float*>(smraw + pr * PAIRA);  // buf0-hi

        if (step > 0) {
            // pair-local GEMM: gates_h[16 x 32] = h_pair[16 x 1024] @ Wres^T
            auto gloadA = [&](int buf, int k0) {
                const uint32_t bo = pA + (uint32_t)(buf * PBUF);
#pragma unroll
                for (int l = 0; l < 2; l++) {
                    int idx = tp + l * 64;      // 0..127 = 16 rows x 8 chunks
                    int rl  = idx >> 3;
                    int chk = idx & 7;
                    int b   = pr * 16 + rl;
                    uint32_t so = (uint32_t)(rl * ASTR + chk * 16);
                    cp16(bo +        so, &hH[(size_t)b * HH + k0 + chk * 8]);
                    cp16(bo + PMID + so, &hM[(size_t)b * HH + k0 + chk * 8]);
                }
                cp_commit();
            };

            gloadA(0, 0);

            for (int kt = 0; kt < 16; kt++) {
                if (kt + 1 < 16) { gloadA((kt + 1) & 1, (kt + 1) * 64); cp_wait1(); }
                else             { cp_wait(); }
                bar_pair(pr + 1);

                const uint32_t aA0 = pA + (uint32_t)((kt & 1) * PBUF);
                const uint32_t aA1 = aA0 + PMID;

#pragma unroll
                for (int s = 0; s < 4; s++) {
                    uint32_t b0f[2][2], b1f[2][2];
                    const uint32_t bOff = (uint32_t)((lane & 7) * WSTR + kt * 128
                                                     + s * 32 + ((lane >> 3) & 1) * 16);
#pragma unroll
                    for (int nt = 0; nt < 2; nt++) {
                        uint32_t na = (uint32_t)((wn * 16 + nt * 8) * WSTR);
                        ldsm2(b0f[nt][0], b0f[nt][1], sbase + SW_H + na + bOff);
                        ldsm2(b1f[nt][0], b1f[nt][1], sbase + SW_M + na + bOff);
                    }
                    const uint32_t aOff = (uint32_t)((lane & 15) * ASTR
                                                     + s * 32 + (lane >> 4) * 16);
                    uint32_t a0[4], a1[4];
                    ldsm4(a0[0], a0[1], a0[2], a0[3], aA0 + aOff);
                    ldsm4(a1[0], a1[1], a1[2], a1[3], aA1 + aOff);
#pragma unroll
                    for (int nt = 0; nt < 2; nt++) {
                        MMA_BF16(acc[nt], a0, b0f[nt]);
                        MMA_BF16(acc[nt], a0, b1f[nt]);
                        MMA_BF16(acc[nt], a1, b0f[nt]);
                    }
                }
            }
            bar_pair(pr + 1);   // partner warp done reading buf0 before alias
        } else {
            cp_wait();          // gx stage
            bar_pair(pr + 1);
        }

        // dump accumulators into pair gsum (16 rows x 36 floats, stride 144 B)
#pragma unroll
        for (int nt = 0; nt < 2; nt++) {
            int ml = lane >> 2;                     // 0..7
            int n  = wn * 16 + nt * 8 + 2 * (lane & 3);
            gsum[ml * 36 + n]           = acc[nt][0];
            gsum[ml * 36 + n + 1]       = acc[nt][1];
            gsum[(ml + 8) * 36 + n]     = acc[nt][2];
            gsum[(ml + 8) * 36 + n + 1] = acc[nt][3];
        }
        bar_pair(pr + 1);

        // cell: pair's 16 batches x 8 hidden units
#pragma unroll
        for (int q = 0; q < 2; q++) {
            int idx = tp + q * 64;      // 0..127
            int rl  = idx >> 3;         // 0..15
            int jj  = idx & 7;
            int b   = pr * 16 + rl;
            float4 g  = *reinterpret_cast<float4*>(&gsum[rl * 36 + jj * 4]);
            float4 gv = *reinterpret_cast<float4*>(smraw + SGX + b * 128 + jj * 16);
            float gi = g.x + gv.x;
            float gf = g.y + gv.y;
            float gg = g.z + gv.z;
            float go = g.w + gv.w;
            float si = 1.f / (1.f + expf(-gi));
            float sf = 1.f / (1.f + expf(-gf));
            float so = 1.f / (1.f + expf(-go));
            float tg = tanhf(gg);
            float cn = sf * c_sm[b * 8 + jj] + si * tg;
            float hn = so * tanhf(cn);
            c_sm[b * 8 + jj] = cn;
            int j = (col0 >> 2) + jj;
            bf16 hh, hm;
            split_bf(hn, hh, hm);
            oH[(size_t)b * HH + j] = hh;
            oM[(size_t)b * HH + j] = hm;
        }

        if (step < 17) {
            __syncthreads();    // all pairs' h stores done
            if (tid == 0) {
                const unsigned int R = s_phase + (unsigned int)step;
                unsigned int t1 = atom_add_acqrel(&g_grp[grp], 1);
                if (t1 == R * 16 + 15) {
                    unsigned int t2 = atom_add_acqrel(&g_root, 1);
                    if (t2 == R * 8 + 7) atom_add_acqrel(&g_phase, 1);
                }
                while (ld_acquire(&g_phase) <= R) { }
            }
            __syncthreads();
        }
    }
}

// ---------------------------------------------------------------------------
// Prep kernels (fp32 -> split bf16), grid-stride
// ---------------------------------------------------------------------------
__global__ void prep_main(const float* __restrict__ feats,
                          const float* __restrict__ fc1_w,
                          bf16* __restrict__ featsH, bf16* __restrict__ featsM,
                          bf16* __restrict__ fc1H,   bf16* __restrict__ fc1M)
{
    const int stride = gridDim.x * blockDim.x;
    int g = blockIdx.x * blockDim.x + threadIdx.x;
    for (int i = g; i < NB_FEATS / 4; i += stride) {
        float4 v = reinterpret_cast<const float4*>(feats)[i];
        __nv_bfloat162 h0, h1, m0, m1;
        split_bf(v.x, h0.x, m0.x); split_bf(v.y, h0.y, m0.y);
        split_bf(v.z, h1.x, m1.x); split_bf(v.w, h1.y, m1.y);
        reinterpret_cast<__nv_bfloat162*>(featsH)[2 * i]     = h0;
        reinterpret_cast<__nv_bfloat162*>(featsH)[2 * i + 1] = h1;
        reinterpret_cast<__nv_bfloat162*>(featsM)[2 * i]     = m0;
        reinterpret_cast<__nv_bfloat162*>(featsM)[2 * i + 1] = m1;
    }
    for (int i = g; i < NB_FC1 / 4; i += stride) {
        float4 v = reinterpret_cast<const float4*>(fc1_w)[i];
        __nv_bfloat162 h0, h1, m0, m1;
        split_bf(v.x, h0.x, m0.x); split_bf(v.y, h0.y, m0.y);
        split_bf(v.z, h1.x, m1.x); split_bf(v.w, h1.y, m1.y);
        reinterpret_cast<__nv_bfloat162*>(fc1H)[2 * i]     = h0;
        reinterpret_cast<__nv_bfloat162*>(fc1H)[2 * i + 1] = h1;
        reinterpret_cast<__nv_bfloat162*>(fc1M)[2 * i]     = m0;
        reinterpret_cast<__nv_bfloat162*>(fc1M)[2 * i + 1] = m1;
    }
}

__device__ __forceinline__ void perm_split_body(const float* s, bf16* H, bf16* M,
                                                int cols, int i)
{
    int cols4 = cols >> 2;
    int p  = i / cols4;
    int cq = i % cols4;
    int sr = (p & 3) * HH + (p >> 2);
    float4 v = *reinterpret_cast<const float4*>(&s[(size_t)sr * cols + cq * 4]);
    __nv_bfloat162 h0, h1, m0, m1;
    split_bf(v.x, h0.x, m0.x); split_bf(v.y, h0.y, m0.y);
    split_bf(v.z, h1.x, m1.x); split_bf(v.w, h1.y, m1.y);
    size_t o = (size_t)p * cols + cq * 4;
    *reinterpret_cast<__nv_bfloat162*>(&H[o])     = h0;
    *reinterpret_cast<__nv_bfloat162*>(&H[o + 2]) = h1;
    *reinterpret_cast<__nv_bfloat162*>(&M[o])     = m0;
    *reinterpret_cast<__nv_bfloat162*>(&M[o + 2]) = m1;
}

__global__ void prep_early(const float* __restrict__ roll_wih,
                           const float* __restrict__ lh,
                           const float* __restrict__ rh,
                           const float* __restrict__ fch_w,
                           bf16* rwihH, bf16* rwihM,
                           bf16* handsH, bf16* handsM,
                           bf16* fchwH, bf16* fchwM)
{
    const int stride = gridDim.x * blockDim.x;
    int g = blockIdx.x * blockDim.x + threadIdx.x;
    const int N_IH = 4 * HH * (2 * HH / 4);
    for (int i = g; i < N_IH; i += stride) perm_split_body(roll_wih, rwihH, rwihM, 2*HH, i);
    for (int i = g; i < SS * BB * HPAD; i += stride) {
        int col = i % HPAD, row = i / HPAD;
        float v = 0.f;
        if (col < HANDD)          v = lh[row * HANDD + col];
        else if (col < 2 * HANDD) v = rh[row * HANDD + (col - HANDD)];
        bf16 h, m; split_bf(v, h, m);
        handsH[i] = h; handsM[i] = m;
    }
    for (int i = g; i < HH * HPAD; i += stride) {
        int col = i % HPAD, row = i / HPAD;
        float v = (col < 2 * HANDD) ? fch_w[row * 2 * HANDD + col] : 0.f;
        bf16 h, m; split_bf(v, h, m);
        fchwH[i] = h; fchwM[i] = m;
    }
}

// late preps: uwih, rwhh, uwhh (needed before gatesxu / persistent)
__global__ void prep_late(const float* __restrict__ u_wih,
                          const float* __restrict__ roll_whh,
                          const float* __restrict__ u_whh,
                          bf16* uwihH, bf16* uwihM,
                          bf16* rwhhH, bf16* rwhhM, bf16* uwhhH, bf16* uwhhM)
{
    const int stride = gridDim.x * blockDim.x;
    int g = blockIdx.x * blockDim.x + threadIdx.x;
    const int N_IH = 4 * HH * (2 * HH / 4);
    const int N_HH = 4 * HH * (HH / 4);
    for (int i = g; i < N_IH; i += stride) perm_split_body(u_wih,    uwihH, uwihM, 2*HH, i);
    for (int i = g; i < N_HH; i += stride) perm_split_body(roll_whh, rwhhH, rwhhM, HH, i);
    for (int i = g; i < N_HH; i += stride) perm_split_body(u_whh,    uwhhH, uwhhM, HH, i);
}

// cls split (overlaps the persistent kernel)
__global__ void cls_split_bf(const float* __restrict__ w,
                             bf16* __restrict__ H, bf16* __restrict__ M)
{
    int i = blockIdx.x * blockDim.x + threadIdx.x;
    if (i >= 1024 * (HH / 4)) return;
    int rr = i / (HH / 4), cq = i % (HH / 4);
    float4 v = (rr < CC)
        ? *reinterpret_cast<const float4*>(&w[(size_t)rr * HH + cq * 4])
        : make_float4(0.f, 0.f, 0.f, 0.f);
    __nv_bfloat162 h0, h1, m0, m1;
    split_bf(v.x, h0.x, m0.x); split_bf(v.y, h0.y, m0.y);
    split_bf(v.z, h1.x, m1.x); split_bf(v.w, h1.y, m1.y);
    size_t o = (size_t)rr * HH + cq * 4;
    *reinterpret_cast<__nv_bfloat162*>(&H[o])     = h0;
    *reinterpret_cast<__nv_bfloat162*>(&H[o + 2]) = h1;
    *reinterpret_cast<__nv_bfloat162*>(&M[o])     = m0;
    *reinterpret_cast<__nv_bfloat162*>(&M[o + 2]) = m1;
}

__global__ void row_stats(const float* __restrict__ out,
                          const int* __restrict__ act,
                          float* __restrict__ pred_f,
                          float* __restrict__ lossrow)
{
    const int b = blockIdx.x;
    const float* row = out + (size_t)b * CC;
    __shared__ float smax[128];
    __shared__ int   sidx[128];
    __shared__ float ssum[128];
    const int t = threadIdx.x;

    float best = -INFINITY;
    int bidx = 0;
    for (int j = t; j < CC; j += 128) {
        float v = row[j];
        if (v > best) { best = v; bidx = j; }
    }
    smax[t] = best; sidx[t] = bidx;
    __syncthreads();
    for (int s = 64; s > 0; s >>= 1) {
        if (t < s) {
            float v2 = smax[t + s]; int i2 = sidx[t + s];
            if (v2 > smax[t] || (v2 == smax[t] && i2 < sidx[t])) {
                smax[t] = v2; sidx[t] = i2;
            }
        }
        __syncthreads();
    }
    const float rowmax = smax[0];
    const int   rowarg = sidx[0];

    float lsum = 0.f;
    for (int j = t; j < CC; j += 128) lsum += expf(row[j] - rowmax);
    ssum[t] = lsum;
    __syncthreads();
    for (int s = 64; s > 0; s >>= 1) {
        if (t < s) ssum[t] += ssum[t + s];
        __syncthreads();
    }
    if (t == 0) {
        float logz = rowmax + logf(ssum[0]);
        lossrow[b] = logz - row[act[b]];
        if (pred_f) pred_f[b] = (float)rowarg;
    }
}

__global__ void mean_loss(const float* __restrict__ lossrow, float* loss_out)
{
    __shared__ float s[128];
    int t = threadIdx.x;
    s[t] = lossrow[t];
    __syncthreads();
    for (int st = 64; st > 0; st >>= 1) {
        if (t < st) s[t] += s[t + st];
        __syncthreads();
    }
    if (t == 0) *loss_out = s[0] / (float)BB;
}

// ---------------------------------------------------------------------------
// Launch
// ---------------------------------------------------------------------------
#define GSM 81920

extern "C" void kernel_launch(void* const* d_in, const int* in_sizes, int n_in,
                              void* d_out, int out_size)
{
    const float* feats    = (const float*)d_in[0];
    const float* lh       = (const float*)d_in[1];
    const float* rh       = (const float*)d_in[2];
    const int*   act      = (const int*)  d_in[3];
    const float* fc1_w    = (const float*)d_in[4];
    const float* fc1_b    = (const float*)d_in[5];
    const float* fch_w    = (const float*)d_in[6];
    const float* fch_b    = (const float*)d_in[7];
    const float* roll_wih = (const float*)d_in[8];
    const float* roll_whh = (const float*)d_in[9];
    const float* roll_bih = (const float*)d_in[10];
    const float* roll_bhh = (const float*)d_in[11];
    const float* u_wih    = (const float*)d_in[12];
    const float* u_whh    = (const float*)d_in[13];
    const float* u_bih    = (const float*)d_in[14];
    const float* u_bhh    = (const float*)d_in[15];
    const float* cls_w    = (const float*)d_in[16];
    const float* cls_b    = (const float*)d_in[17];
    float* out = (float*)d_out;

    cudaFuncSetAttribute(gemm_bf<0, 1>, cudaFuncAttributeMaxDynamicSharedMemorySize, GSM);
    cudaFuncSetAttribute(gemm_bf<1, 0>, cudaFuncAttributeMaxDynamicSharedMemorySize, GSM);
    cudaFuncSetAttribute(gemm_bf<0, 0>, cudaFuncAttributeMaxDynamicSharedMemorySize, GSM);
    cudaFuncSetAttribute(lstm_persistent, cudaFuncAttributeMaxDynamicSharedMemorySize, PSM);

    static cudaStream_t s1 = nullptr;
    static cudaEvent_t evFork = nullptr, evS1 = nullptr, evB = nullptr,
                       evC = nullptr, evD = nullptr;
    if (!s1) {
        cudaStreamCreateWithFlags(&s1, cudaStreamNonBlocking);
        cudaEventCreateWithFlags(&evFork, cudaEventDisableTiming);
        cudaEventCreateWithFlags(&evS1,   cudaEventDisableTiming);
        cudaEventCreateWithFlags(&evB,    cudaEventDisableTiming);
        cudaEventCreateWithFlags(&evC,    cudaEventDisableTiming);
        cudaEventCreateWithFlags(&evD,    cudaEventDisableTiming);
    }

    float* sc = nullptr;
    cudaGetSymbolAddress((void**)&sc, g_scratch);

    bf16* featsH = (bf16*)(sc + OFF_FEATSH); bf16* featsM = (bf16*)(sc + OFF_FEATSM);
    bf16* xH     = (bf16*)(sc + OFF_XH);     bf16* xM     = (bf16*)(sc + OFF_XM);
    float* gatesx  = sc + OFF_GATESX;
    float* gatesxu = sc + OFF_GATESXU;
    bf16* h0H = (bf16*)(sc + OFF_H0H); bf16* h0M = (bf16*)(sc + OFF_H0M);
    bf16* h1H = (bf16*)(sc + OFF_H1H); bf16* h1M = (bf16*)(sc + OFF_H1M);
    bf16* handsH = (bf16*)(sc + OFF_HANDSH); bf16* handsM = (bf16*)(sc + OFF_HANDSM);
    bf16* fc1H   = (bf16*)(sc + OFF_FC1H);   bf16* fc1M   = (bf16*)(sc + OFF_FC1M);
    bf16* fchwH  = (bf16*)(sc + OFF_FCHWH);  bf16* fchwM  = (bf16*)(sc + OFF_FCHWM);
    bf16* rwihH  = (bf16*)(sc + OFF_RWIHH);  bf16* rwihM  = (bf16*)(sc + OFF_RWIHM);
    bf16* rwhhH  = (bf16*)(sc + OFF_RWHHH);  bf16* rwhhM  = (bf16*)(sc + OFF_RWHHM);
    bf16* uwihH  = (bf16*)(sc + OFF_UWIHH);  bf16* uwihM  = (bf16*)(sc + OFF_UWIHM);
    bf16* uwhhH  = (bf16*)(sc + OFF_UWHHH);  bf16* uwhhM  = (bf16*)(sc + OFF_UWHHM);
    bf16* clsH   = (bf16*)(sc + OFF_CLSH);   bf16* clsM   = (bf16*)(sc + OFF_CLSM);
    float* lossrow = sc + OFF_LOSSROW;

    // ---- fork side stream ----
    cudaEventRecord(evFork, 0);
    cudaStreamWaitEvent(s1, evFork, 0);

    // side: early preps -> hproj -> evS1; late preps (overlap gates) -> evC;
    //       cls split (overlaps persistent) -> evD
    prep_early<<<296, 256, 0, s1>>>(roll_wih, lh, rh, fch_w,
                                    rwihH, rwihM, handsH, handsM, fchwH, fchwM);
    gemm_bf<0,1><<<dim3(8,16), 256, GSM, s1>>>(handsH, handsM, HPAD,
                                               fchwH, fchwM, HPAD,
                                               nullptr, xH + HH, xM + HH, 2*HH,
                                               fch_b, nullptr, HH, HPAD);
    cudaEventRecord(evS1, s1);
    prep_late<<<296, 256, 0, s1>>>(u_wih, roll_whh, u_whh,
                                   uwihH, uwihM, rwhhH, rwhhM, uwhhH, uwhhM);
    cudaEventRecord(evC, s1);
    cls_split_bf<<<(1024*(HH/4) + 255)/256, 256, 0, s1>>>(cls_w, clsH, clsM);
    cudaEventRecord(evD, s1);

    // main: critical path
    prep_main<<<296, 256>>>(feats, fc1_w, featsH, featsM, fc1H, fc1M);
    gemm_bf<0,1><<<dim3(8,16), 256, GSM>>>(featsH, featsM, FEATD,
                                           fc1H, fc1M, FEATD,
                                           nullptr, xH, xM, 2*HH,
                                           fc1_b, nullptr, HH, FEATD);
    // gates (needs hproj + rwih)
    cudaStreamWaitEvent(0, evS1, 0);
    gemm_bf<1,0><<<dim3(32,16), 256, GSM>>>(xH, xM, 2*HH,
                                            rwihH, rwihM, 2*HH,
                                            gatesx, nullptr, nullptr, 4*HH,
                                            roll_bih, roll_bhh, 4*HH, 2*HH);
    // gatesxu on main (needs uwih from prep_late)
    cudaStreamWaitEvent(0, evC, 0);
    gemm_bf<1,0><<<dim3(32,1), 256, GSM>>>(xH + (size_t)(SS-1)*BB*2*HH,
                                           xM + (size_t)(SS-1)*BB*2*HH, 2*HH,
                                           uwihH, uwihM, 2*HH,
                                           gatesxu, nullptr, nullptr, 4*HH,
                                           u_bih, u_bhh, 4*HH, 2*HH);

    // recurrence (cls split still running on side — independent)
    lstm_persistent<<<128, PTHREADS, PSM>>>(rwhhH, rwhhM, uwhhH, uwhhM,
                                            gatesx, gatesxu,
                                            h0H, h0M, h1H, h1M);

    // classifier (needs cls split)
    cudaStreamWaitEvent(0, evD, 0);
    gemm_bf<0,0><<<dim3(8,1), 256, GSM>>>(h0H, h0M, HH,
                                          clsH, clsM, HH,
                                          out, nullptr, nullptr, CC,
                                          cls_b, nullptr, CC, HH);

    // stats
    float* pred_f = (out_size >= BB * CC + BB)     ? out + BB * CC : nullptr;
    float* loss_p = (out_size >= BB * CC + BB + 1) ? out + BB * CC + BB : nullptr;
    row_stats<<<BB, 128>>>(out, act, pred_f, lossrow);
    if (loss_p) mean_loss<<<1, 128>>>(lossrow, loss_p);
}

// round 15
// speedup vs baseline: 1.0382x; 1.0382x over previous
#include <cuda_runtime.h>
#include <cuda_bf16.h>
#include <math.h>
#include <stdint.h>

#define SS    16
#define BB    128
#define FEATD 2048
#define HANDD 63
#define HH    1024
#define CC    1000
#define HPAD  128

// ---------------------------------------------------------------------------
// Scratch layout
// ---------------------------------------------------------------------------
#define NB_FEATS (SS*BB*FEATD)
#define NB_X     (SS*BB*2*HH)
#define NB_HANDS (SS*BB*HPAD)
#define NB_FC1   (HH*FEATD)
#define NB_FCHW  (HH*HPAD)
#define NB_RWIH  (4*HH*2*HH)
#define NB_RWHH  (4*HH*HH)
#define NB_CLS   (1024*HH)
#define NB_H     (BB*HH)

#define OFF_FEATSH  0
#define OFF_FEATSM  (OFF_FEATSH + NB_FEATS/2)
#define OFF_XH      (OFF_FEATSM + NB_FEATS/2)
#define OFF_XM      (OFF_XH     + NB_X/2)
#define OFF_GATESX  (OFF_XM     + NB_X/2)
#define OFF_GATESXU (OFF_GATESX + SS*BB*4*HH)
#define OFF_H0H     (OFF_GATESXU+ BB*4*HH)
#define OFF_H0M     (OFF_H0H    + NB_H/2)
#define OFF_H1H     (OFF_H0M    + NB_H/2)
#define OFF_H1M     (OFF_H1H    + NB_H/2)
#define OFF_HANDSH  (OFF_H1M    + NB_H/2)
#define OFF_HANDSM  (OFF_HANDSH + NB_HANDS/2)
#define OFF_FC1H    (OFF_HANDSM + NB_HANDS/2)
#define OFF_FC1M    (OFF_FC1H   + NB_FC1/2)
#define OFF_FCHWH   (OFF_FC1M   + NB_FC1/2)
#define OFF_FCHWM   (OFF_FCHWH  + NB_FCHW/2)
#define OFF_RWIHH   (OFF_FCHWM  + NB_FCHW/2)
#define OFF_RWIHM   (OFF_RWIHH  + NB_RWIH/2)
#define OFF_RWHHH   (OFF_RWIHM  + NB_RWIH/2)
#define OFF_RWHHM   (OFF_RWHHH  + NB_RWHH/2)
#define OFF_UWIHH   (OFF_RWHHM  + NB_RWHH/2)
#define OFF_UWIHM   (OFF_UWIHH  + NB_RWIH/2)
#define OFF_UWHHH   (OFF_UWIHM  + NB_RWIH/2)
#define OFF_UWHHM   (OFF_UWHHH  + NB_RWHH/2)
#define OFF_CLSH    (OFF_UWHHM  + NB_RWHH/2)
#define OFF_CLSM    (OFF_CLSH   + NB_CLS/2)
#define OFF_LOSSROW (OFF_CLSM   + NB_CLS/2)
#define SCRATCH_TOT (OFF_LOSSROW + BB)

__device__ __align__(16) float g_scratch[SCRATCH_TOT];

// tree grid-barrier state (monotone counters; snapshot at entry -> replay-safe)
__device__ unsigned int g_grp[8];
__device__ unsigned int g_root  = 0;
__device__ unsigned int g_phase = 0;

typedef __nv_bfloat16 bf16;

// ---------------------------------------------------------------------------
// helpers
// ---------------------------------------------------------------------------
__device__ __forceinline__ void split_bf(float v, bf16& h, bf16& m)
{
    h = __float2bfloat16_rn(v);
    m = __float2bfloat16_rn(v - __bfloat162float(h));
}

#define MMA_BF16(d, a, b)                                                     \
    asm volatile(                                                             \
        "mma.sync.aligned.m16n8k16.row.col.f32.bf16.bf16.f32 "                \
        "{%0,%1,%2,%3},{%4,%5,%6,%7},{%8,%9},{%0,%1,%2,%3};"                  \
        : "+f"(d[0]), "+f"(d[1]), "+f"(d[2]), "+f"(d[3])                      \
        : "r"(a[0]), "r"(a[1]), "r"(a[2]), "r"(a[3]), "r"(b[0]), "r"(b[1]))

__device__ __forceinline__ void ldsm4(uint32_t& r0, uint32_t& r1,
                                      uint32_t& r2, uint32_t& r3, uint32_t addr)
{
    asm volatile("ldmatrix.sync.aligned.m8n8.x4.shared.b16 {%0,%1,%2,%3}, [%4];"
                 : "=r"(r0), "=r"(r1), "=r"(r2), "=r"(r3) : "r"(addr));
}
__device__ __forceinline__ void ldsm2(uint32_t& r0, uint32_t& r1, uint32_t addr)
{
    asm volatile("ldmatrix.sync.aligned.m8n8.x2.shared.b16 {%0,%1}, [%2];"
                 : "=r"(r0), "=r"(r1) : "r"(addr));
}

__device__ __forceinline__ void cp16(uint32_t dst, const void* src)
{
    asm volatile("cp.async.cg.shared.global [%0], [%1], 16;" :: "r"(dst), "l"(src));
}
__device__ __forceinline__ void cp_commit() { asm volatile("cp.async.commit_group;"); }
__device__ __forceinline__ void cp_wait()   { asm volatile("cp.async.wait_group 0;"); }
__device__ __forceinline__ void cp_wait1()  { asm volatile("cp.async.wait_group 1;"); }

__device__ __forceinline__ unsigned int atom_add_acqrel(unsigned int* p, unsigned int v)
{
    unsigned int old;
    asm volatile("atom.acq_rel.gpu.global.add.u32 %0, [%1], %2;"
                 : "=r"(old) : "l"(p), "r"(v) : "memory");
    return old;
}
__device__ __forceinline__ unsigned int ld_acquire(unsigned int* p)
{
    unsigned int v;
    asm volatile("ld.acquire.gpu.global.u32 %0, [%1];" : "=r"(v) : "l"(p) : "memory");
    return v;
}

// ---------------------------------------------------------------------------
// bf16x2-split GEMM (3 products): C = A*W^T (+bias)  [proven, unchanged]
// ---------------------------------------------------------------------------
template<int PERMBIAS, int SPLITOUT>
__global__ void __launch_bounds__(256, 2)
gemm_bf(const bf16* __restrict__ AH, const bf16* __restrict__ AM, int lda,
        const bf16* __restrict__ WH, const bf16* __restrict__ WM, int ldw,
        float* __restrict__ Cf, bf16* __restrict__ CbH, bf16* __restrict__ CbM,
        int ldc, const float* __restrict__ b1, const float* __restrict__ b2,
        int Nstore, int K)
{
    extern __shared__ __align__(16) char smraw[];
    const uint32_t sbase = (uint32_t)__cvta_generic_to_shared(smraw);

    const int tid  = threadIdx.x;
    const int lane = tid & 31;
    const int warp = tid >> 5;
    const int wm   = warp >> 2;
    const int wn   = warp & 3;
    const int row0 = blockIdx.y * 128;
    const int col0 = blockIdx.x * 128;

    float acc[4][4][4];
#pragma unroll
    for (int i = 0; i < 4; i++)
#pragma unroll
        for (int j = 0; j < 4; j++)
#pragma unroll
            for (int q = 0; q < 4; q++) acc[i][j][q] = 0.f;

    const int r  = tid >> 2;
    const int ch = tid & 3;

    auto gload = [&](int buf, int k0) {
        const uint32_t bo = (uint32_t)(buf * 40960);
#pragma unroll
        for (int l = 0; l < 2; l++) {
            int rr = r + l * 64;
            uint32_t so = (uint32_t)(rr * 80 + ch * 16);
            cp16(sbase + bo +         so, &AH[(size_t)(row0 + rr) * lda + k0 + ch * 8]);
            cp16(sbase + bo + 10240 + so, &AM[(size_t)(row0 + rr) * lda + k0 + ch * 8]);
            cp16(sbase + bo + 20480 + so, &WH[(size_t)(col0 + rr) * ldw + k0 + ch * 8]);
            cp16(sbase + bo + 30720 + so, &WM[(size_t)(col0 + rr) * ldw + k0 + ch * 8]);
        }
        cp_commit();
    };

    const int nk = K / 32;
    gload(0, 0);
    cp_wait();
    __syncthreads();

    for (int kt = 0; kt < nk; kt++) {
        const int cur = kt & 1;
        if (kt + 1 < nk) gload(cur ^ 1, (kt + 1) * 32);

        const uint32_t bo  = (uint32_t)(cur * 40960);
        const uint32_t aA0 = sbase + bo;
        const uint32_t aA1 = sbase + bo + 10240;
        const uint32_t aB0 = sbase + bo + 20480;
        const uint32_t aB1 = sbase + bo + 30720;

#pragma unroll
        for (int s = 0; s < 2; s++) {
            uint32_t b0f[4][2], b1f[4][2];
            const uint32_t bOff = (uint32_t)((lane & 7) * 80 + s * 32 + ((lane >> 3) & 1) * 16);
#pragma unroll
            for (int nt = 0; nt < 4; nt++) {
                uint32_t na = (uint32_t)((wn * 32 + nt * 8) * 80);
                ldsm2(b0f[nt][0], b0f[nt][1], aB0 + na + bOff);
                ldsm2(b1f[nt][0], b1f[nt][1], aB1 + na + bOff);
            }
            const uint32_t aOff = (uint32_t)((lane & 15) * 80 + s * 32 + (lane >> 4) * 16);
#pragma unroll
            for (int mt = 0; mt < 4; mt++) {
                uint32_t ma = (uint32_t)((wm * 64 + mt * 16) * 80);
                uint32_t a0[4], a1[4];
                ldsm4(a0[0], a0[1], a0[2], a0[3], aA0 + ma + aOff);
                ldsm4(a1[0], a1[1], a1[2], a1[3], aA1 + ma + aOff);
#pragma unroll
                for (int nt = 0; nt < 4; nt++) {
                    MMA_BF16(acc[mt][nt], a0, b0f[nt]);
                    MMA_BF16(acc[mt][nt], a0, b1f[nt]);
                    MMA_BF16(acc[mt][nt], a1, b0f[nt]);
                }
            }
        }

        if (kt + 1 < nk) { cp_wait(); __syncthreads(); }
    }

#pragma unroll
    for (int mt = 0; mt < 4; mt++)
#pragma unroll
        for (int nt = 0; nt < 4; nt++) {
            int m = row0 + wm * 64 + mt * 16 + (lane >> 2);
            int n = col0 + wn * 32 + nt * 8 + 2 * (lane & 3);
            if (n + 1 >= Nstore) continue;
            float bv0 = 0.f, bv1 = 0.f;
            int bi0 = PERMBIAS ? ((n & 3) * HH + (n >> 2)) : n;
            int bi1 = PERMBIAS ? (((n + 1) & 3) * HH + ((n + 1) >> 2)) : (n + 1);
            if (b1) { bv0 += b1[bi0]; bv1 += b1[bi1]; }
            if (b2) { bv0 += b2[bi0]; bv1 += b2[bi1]; }
            float v00 = acc[mt][nt][0] + bv0, v01 = acc[mt][nt][1] + bv1;
            float v10 = acc[mt][nt][2] + bv0, v11 = acc[mt][nt][3] + bv1;
            if (SPLITOUT) {
                __nv_bfloat162 h0, m0, h1, m1;
                split_bf(v00, h0.x, m0.x); split_bf(v01, h0.y, m0.y);
                split_bf(v10, h1.x, m1.x); split_bf(v11, h1.y, m1.y);
                *reinterpret_cast<__nv_bfloat162*>(&CbH[(size_t)m * ldc + n])       = h0;
                *reinterpret_cast<__nv_bfloat162*>(&CbM[(size_t)m * ldc + n])       = m0;
                *reinterpret_cast<__nv_bfloat162*>(&CbH[(size_t)(m + 8) * ldc + n]) = h1;
                *reinterpret_cast<__nv_bfloat162*>(&CbM[(size_t)(m + 8) * ldc + n]) = m1;
            } else {
                *reinterpret_cast<float2*>(&Cf[(size_t)m * ldc + n])       = make_float2(v00, v01);
                *reinterpret_cast<float2*>(&Cf[(size_t)(m + 8) * ldc + n]) = make_float2(v10, v11);
            }
        }
}

// ---------------------------------------------------------------------------
// Persistent LSTM recurrence — R13 proven version (512 threads, BK=64,
// A-row stride 144, conflict-free weight stride 2096, tree grid barrier)
// + poll backoff (__nanosleep) to kill the spin convoy on g_phase.
//
// smem (dyn, 228352 B):
//   0      : A stages, 2 bufs x (H 18432 | M 18432) = 73728  (gsum aliases buf0)
//   73728  : W_H  32 rows x 2096 B                  = 67072
//   140800 : W_M  32 rows x 2096 B                  = 67072
//   207872 : gx stage 128 rows x 128 B              = 16384
//   224256 : c    128 x 8 floats                    = 4096
// ---------------------------------------------------------------------------
#define PSM  228352
#define ABUF 36864
#define ASTR 144
#define SW_H 73728
#define SW_M 140800
#define SGX  207872
#define SCC  224256
#define WSTR 2096
#define PTHREADS 512

__global__ void __launch_bounds__(PTHREADS)
lstm_persistent(const bf16* __restrict__ rwhhH, const bf16* __restrict__ rwhhM,
                const bf16* __restrict__ uwhhH, const bf16* __restrict__ uwhhM,
                const float* __restrict__ gatesx,   // [16][128][4096] permuted
                const float* __restrict__ gatesxu,  // [128][4096] permuted
                bf16* __restrict__ h0H, bf16* __restrict__ h0M,
                bf16* __restrict__ h1H, bf16* __restrict__ h1M)
{
    extern __shared__ __align__(16) char smraw[];
    const uint32_t sbase = (uint32_t)__cvta_generic_to_shared(smraw);
    float* gsum = reinterpret_cast<float*>(smraw);          // aliases A buf 0
    float* c_sm = reinterpret_cast<float*>(smraw + SCC);

    const int tid  = threadIdx.x;
    const int lane = tid & 31;
    const int warp = tid >> 5;          // 0..15
    const int wm   = warp >> 1;         // 0..7 over M
    const int wn   = warp & 1;          // 0..1 over N
    const int col0 = blockIdx.x * 32;
    const int grp  = blockIdx.x >> 4;   // 0..7

    __shared__ unsigned int s_phase;
    if (tid == 0) s_phase = g_phase;

#pragma unroll
    for (int q = 0; q < 2; q++) c_sm[tid + q * PTHREADS] = 0.f;

    auto load_weights = [&](const bf16* wH, const bf16* wM) {
        for (int i = tid; i < 4096; i += PTHREADS) {
            int row = i >> 7;
            int chk = i & 127;
            uint32_t so = (uint32_t)(row * WSTR + chk * 16);
            cp16(sbase + SW_H + so, &wH[(size_t)(col0 + row) * HH + chk * 8]);
            cp16(sbase + SW_M + so, &wM[(size_t)(col0 + row) * HH + chk * 8]);
        }
        cp_commit();
        cp_wait();
        __syncthreads();
    };
    load_weights(rwhhH, rwhhM);

    for (int step = 0; step < 18; step++) {
        const bf16* hH = (step & 1) ? h1H : h0H;
        const bf16* hM = (step & 1) ? h1M : h0M;
        bf16* oH = (step & 1) ? h0H : h1H;
        bf16* oM = (step & 1) ? h0M : h1M;
        const float* gx = (step < SS) ? gatesx + (size_t)step * BB * 4 * HH
                                      : gatesxu;

        if (step == SS) load_weights(uwhhH, uwhhM);

        // stage this step's gx slice (128 rows x 128 B) into smem early
        {
#pragma unroll
            for (int l = 0; l < 2; l++) {
                int idx = tid + l * PTHREADS;
                int b   = idx >> 3;
                int chk = idx & 7;
                cp16(sbase + SGX + (uint32_t)(b * 128 + chk * 16),
                     &gx[(size_t)b * (4 * HH) + col0 + chk * 4]);
            }
            cp_commit();
        }

        float acc[2][4];
#pragma unroll
        for (int j = 0; j < 2; j++)
#pragma unroll
            for (int q = 0; q < 4; q++) acc[j][q] = 0.f;

        if (step > 0) {
            // ---- GEMM: gates_h[128 x 32] = h[128 x 1024] @ Wres^T, BK=64 ----
            auto gloadA = [&](int buf, int k0) {
                const uint32_t bo = (uint32_t)(buf * ABUF);
#pragma unroll
                for (int l = 0; l < 2; l++) {
                    int idx = tid + l * PTHREADS;     // 0..1023
                    int row = idx >> 3;
                    int chk = idx & 7;
                    uint32_t so = (uint32_t)(row * ASTR + chk * 16);
                    cp16(sbase + bo +         so, &hH[(size_t)row * HH + k0 + chk * 8]);
                    cp16(sbase + bo + 18432 + so, &hM[(size_t)row * HH + k0 + chk * 8]);
                }
                cp_commit();
            };

            gloadA(0, 0);

            for (int kt = 0; kt < 16; kt++) {
                if (kt + 1 < 16) { gloadA((kt + 1) & 1, (kt + 1) * 64); cp_wait1(); }
                else             { cp_wait(); }
                __syncthreads();

                const uint32_t aA0 = sbase + (uint32_t)((kt & 1) * ABUF);
                const uint32_t aA1 = aA0 + 18432;

#pragma unroll
                for (int s = 0; s < 4; s++) {
                    uint32_t b0f[2][2], b1f[2][2];
                    const uint32_t bOff = (uint32_t)((lane & 7) * WSTR + kt * 128
                                                     + s * 32 + ((lane >> 3) & 1) * 16);
#pragma unroll
                    for (int nt = 0; nt < 2; nt++) {
                        uint32_t na = (uint32_t)((wn * 16 + nt * 8) * WSTR);
                        ldsm2(b0f[nt][0], b0f[nt][1], sbase + SW_H + na + bOff);
                        ldsm2(b1f[nt][0], b1f[nt][1], sbase + SW_M + na + bOff);
                    }
                    const uint32_t aOff = (uint32_t)((wm * 16 + (lane & 15)) * ASTR
                                                     + s * 32 + (lane >> 4) * 16);
                    uint32_t a0[4], a1[4];
                    ldsm4(a0[0], a0[1], a0[2], a0[3], aA0 + aOff);
                    ldsm4(a1[0], a1[1], a1[2], a1[3], aA1 + aOff);
#pragma unroll
                    for (int nt = 0; nt < 2; nt++) {
                        MMA_BF16(acc[nt], a0, b0f[nt]);
                        MMA_BF16(acc[nt], a0, b1f[nt]);
                        MMA_BF16(acc[nt], a1, b0f[nt]);
                    }
                }
            }
            __syncthreads();   // all warps done with buf0 before gsum alias write
        } else {
            cp_wait();         // gx stage
            __syncthreads();
        }

        // dump accumulators (gsum aliases A buf 0 — GEMM fully drained)
#pragma unroll
        for (int nt = 0; nt < 2; nt++) {
            int m = wm * 16 + (lane >> 2);
            int n = wn * 16 + nt * 8 + 2 * (lane & 3);
            gsum[m * 36 + n]           = acc[nt][0];
            gsum[m * 36 + n + 1]       = acc[nt][1];
            gsum[(m + 8) * 36 + n]     = acc[nt][2];
            gsum[(m + 8) * 36 + n + 1] = acc[nt][3];
        }
        __syncthreads();

        // cell (gx read from smem stage)
#pragma unroll
        for (int q = 0; q < 2; q++) {
            int idx = tid + q * PTHREADS;
            int b  = idx >> 3;
            int jj = idx & 7;
            float4 g  = *reinterpret_cast<float4*>(&gsum[b * 36 + jj * 4]);
            float4 gv = *reinterpret_cast<float4*>(smraw + SGX + b * 128 + jj * 16);
            float gi = g.x + gv.x;
            float gf = g.y + gv.y;
            float gg = g.z + gv.z;
            float go = g.w + gv.w;
            float si = 1.f / (1.f + expf(-gi));
            float sf = 1.f / (1.f + expf(-gf));
            float so = 1.f / (1.f + expf(-go));
            float tg = tanhf(gg);
            float cn = sf * c_sm[b * 8 + jj] + si * tg;
            float hn = so * tanhf(cn);
            c_sm[b * 8 + jj] = cn;
            int j = (col0 >> 2) + jj;
            bf16 hh, hm;
            split_bf(hn, hh, hm);
            oH[(size_t)b * HH + j] = hh;
            oM[(size_t)b * HH + j] = hm;
        }

        if (step < 17) {
            // tree grid barrier; poll has nanosleep backoff to avoid the
            // 127-CTA spin convoy on the phase line.
            __syncthreads();
            if (tid == 0) {
                const unsigned int R = s_phase + (unsigned int)step;
                unsigned int t1 = atom_add_acqrel(&g_grp[grp], 1);
                if (t1 == R * 16 + 15) {
                    unsigned int t2 = atom_add_acqrel(&g_root, 1);
                    if (t2 == R * 8 + 7) atom_add_acqrel(&g_phase, 1);
                }
                if (ld_acquire(&g_phase) <= R) {           // fast path check
                    while (ld_acquire(&g_phase) <= R) {
                        __nanosleep(64);
                    }
                }
            }
            __syncthreads();
        }
    }
}

// ---------------------------------------------------------------------------
// Prep kernels (fp32 -> split bf16), grid-stride
// ---------------------------------------------------------------------------
__global__ void prep_main(const float* __restrict__ feats,
                          const float* __restrict__ fc1_w,
                          bf16* __restrict__ featsH, bf16* __restrict__ featsM,
                          bf16* __restrict__ fc1H,   bf16* __restrict__ fc1M)
{
    const int stride = gridDim.x * blockDim.x;
    int g = blockIdx.x * blockDim.x + threadIdx.x;
    for (int i = g; i < NB_FEATS / 4; i += stride) {
        float4 v = reinterpret_cast<const float4*>(feats)[i];
        __nv_bfloat162 h0, h1, m0, m1;
        split_bf(v.x, h0.x, m0.x); split_bf(v.y, h0.y, m0.y);
        split_bf(v.z, h1.x, m1.x); split_bf(v.w, h1.y, m1.y);
        reinterpret_cast<__nv_bfloat162*>(featsH)[2 * i]     = h0;
        reinterpret_cast<__nv_bfloat162*>(featsH)[2 * i + 1] = h1;
        reinterpret_cast<__nv_bfloat162*>(featsM)[2 * i]     = m0;
        reinterpret_cast<__nv_bfloat162*>(featsM)[2 * i + 1] = m1;
    }
    for (int i = g; i < NB_FC1 / 4; i += stride) {
        float4 v = reinterpret_cast<const float4*>(fc1_w)[i];
        __nv_bfloat162 h0, h1, m0, m1;
        split_bf(v.x, h0.x, m0.x); split_bf(v.y, h0.y, m0.y);
        split_bf(v.z, h1.x, m1.x); split_bf(v.w, h1.y, m1.y);
        reinterpret_cast<__nv_bfloat162*>(fc1H)[2 * i]     = h0;
        reinterpret_cast<__nv_bfloat162*>(fc1H)[2 * i + 1] = h1;
        reinterpret_cast<__nv_bfloat162*>(fc1M)[2 * i]     = m0;
        reinterpret_cast<__nv_bfloat162*>(fc1M)[2 * i + 1] = m1;
    }
}

__device__ __forceinline__ void perm_split_body(const float* s, bf16* H, bf16* M,
                                                int cols, int i)
{
    int cols4 = cols >> 2;
    int p  = i / cols4;
    int cq = i % cols4;
    int sr = (p & 3) * HH + (p >> 2);
    float4 v = *reinterpret_cast<const float4*>(&s[(size_t)sr * cols + cq * 4]);
    __nv_bfloat162 h0, h1, m0, m1;
    split_bf(v.x, h0.x, m0.x); split_bf(v.y, h0.y, m0.y);
    split_bf(v.z, h1.x, m1.x); split_bf(v.w, h1.y, m1.y);
    size_t o = (size_t)p * cols + cq * 4;
    *reinterpret_cast<__nv_bfloat162*>(&H[o])     = h0;
    *reinterpret_cast<__nv_bfloat162*>(&H[o + 2]) = h1;
    *reinterpret_cast<__nv_bfloat162*>(&M[o])     = m0;
    *reinterpret_cast<__nv_bfloat162*>(&M[o + 2]) = m1;
}

__global__ void prep_early(const float* __restrict__ roll_wih,
                           const float* __restrict__ lh,
                           const float* __restrict__ rh,
                           const float* __restrict__ fch_w,
                           bf16* rwihH, bf16* rwihM,
                           bf16* handsH, bf16* handsM,
                           bf16* fchwH, bf16* fchwM)
{
    const int stride = gridDim.x * blockDim.x;
    int g = blockIdx.x * blockDim.x + threadIdx.x;
    const int N_IH = 4 * HH * (2 * HH / 4);
    for (int i = g; i < N_IH; i += stride) perm_split_body(roll_wih, rwihH, rwihM, 2*HH, i);
    for (int i = g; i < SS * BB * HPAD; i += stride) {
        int col = i % HPAD, row = i / HPAD;
        float v = 0.f;
        if (col < HANDD)          v = lh[row * HANDD + col];
        else if (col < 2 * HANDD) v = rh[row * HANDD + (col - HANDD)];
        bf16 h, m; split_bf(v, h, m);
        handsH[i] = h; handsM[i] = m;
    }
    for (int i = g; i < HH * HPAD; i += stride) {
        int col = i % HPAD, row = i / HPAD;
        float v = (col < 2 * HANDD) ? fch_w[row * 2 * HANDD + col] : 0.f;
        bf16 h, m; split_bf(v, h, m);
        fchwH[i] = h; fchwM[i] = m;
    }
}

__global__ void prep_late(const float* __restrict__ u_wih,
                          const float* __restrict__ roll_whh,
                          const float* __restrict__ u_whh,
                          bf16* uwihH, bf16* uwihM,
                          bf16* rwhhH, bf16* rwhhM, bf16* uwhhH, bf16* uwhhM)
{
    const int stride = gridDim.x * blockDim.x;
    int g = blockIdx.x * blockDim.x + threadIdx.x;
    const int N_IH = 4 * HH * (2 * HH / 4);
    const int N_HH = 4 * HH * (HH / 4);
    for (int i = g; i < N_IH; i += stride) perm_split_body(u_wih,    uwihH, uwihM, 2*HH, i);
    for (int i = g; i < N_HH; i += stride) perm_split_body(roll_whh, rwhhH, rwhhM, HH, i);
    for (int i = g; i < N_HH; i += stride) perm_split_body(u_whh,    uwhhH, uwhhM, HH, i);
}

__global__ void cls_split_bf(const float* __restrict__ w,
                             bf16* __restrict__ H, bf16* __restrict__ M)
{
    int i = blockIdx.x * blockDim.x + threadIdx.x;
    if (i >= 1024 * (HH / 4)) return;
    int rr = i / (HH / 4), cq = i % (HH / 4);
    float4 v = (rr < CC)
        ? *reinterpret_cast<const float4*>(&w[(size_t)rr * HH + cq * 4])
        : make_float4(0.f, 0.f, 0.f, 0.f);
    __nv_bfloat162 h0, h1, m0, m1;
    split_bf(v.x, h0.x, m0.x); split_bf(v.y, h0.y, m0.y);
    split_bf(v.z, h1.x, m1.x); split_bf(v.w, h1.y, m1.y);
    size_t o = (size_t)rr * HH + cq * 4;
    *reinterpret_cast<__nv_bfloat162*>(&H[o])     = h0;
    *reinterpret_cast<__nv_bfloat162*>(&H[o + 2]) = h1;
    *reinterpret_cast<__nv_bfloat162*>(&M[o])     = m0;
    *reinterpret_cast<__nv_bfloat162*>(&M[o + 2]) = m1;
}

__global__ void row_stats(const float* __restrict__ out,
                          const int* __restrict__ act,
                          float* __restrict__ pred_f,
                          float* __restrict__ lossrow)
{
    const int b = blockIdx.x;
    const float* row = out + (size_t)b * CC;
    __shared__ float smax[128];
    __shared__ int   sidx[128];
    __shared__ float ssum[128];
    const int t = threadIdx.x;

    float best = -INFINITY;
    int bidx = 0;
    for (int j = t; j < CC; j += 128) {
        float v = row[j];
        if (v > best) { best = v; bidx = j; }
    }
    smax[t] = best; sidx[t] = bidx;
    __syncthreads();
    for (int s = 64; s > 0; s >>= 1) {
        if (t < s) {
            float v2 = smax[t + s]; int i2 = sidx[t + s];
            if (v2 > smax[t] || (v2 == smax[t] && i2 < sidx[t])) {
                smax[t] = v2; sidx[t] = i2;
            }
        }
        __syncthreads();
    }
    const float rowmax = smax[0];
    const int   rowarg = sidx[0];

    float lsum = 0.f;
    for (int j = t; j < CC; j += 128) lsum += expf(row[j] - rowmax);
    ssum[t] = lsum;
    __syncthreads();
    for (int s = 64; s > 0; s >>= 1) {
        if (t < s) ssum[t] += ssum[t + s];
        __syncthreads();
    }
    if (t == 0) {
        float logz = rowmax + logf(ssum[0]);
        lossrow[b] = logz - row[act[b]];
        if (pred_f) pred_f[b] = (float)rowarg;
    }
}

__global__ void mean_loss(const float* __restrict__ lossrow, float* loss_out)
{
    __shared__ float s[128];
    int t = threadIdx.x;
    s[t] = lossrow[t];
    __syncthreads();
    for (int st = 64; st > 0; st >>= 1) {
        if (t < st) s[t] += s[t + st];
        __syncthreads();
    }
    if (t == 0) *loss_out = s[0] / (float)BB;
}

// ---------------------------------------------------------------------------
// Launch — two-branch graph; gatesxu overlaps gates; cls split overlaps
// the persistent kernel.
// ---------------------------------------------------------------------------
#define GSM 81920

extern "C" void kernel_launch(void* const* d_in, const int* in_sizes, int n_in,
                              void* d_out, int out_size)
{
    const float* feats    = (const float*)d_in[0];
    const float* lh       = (const float*)d_in[1];
    const float* rh       = (const float*)d_in[2];
    const int*   act      = (const int*)  d_in[3];
    const float* fc1_w    = (const float*)d_in[4];
    const float* fc1_b    = (const float*)d_in[5];
    const float* fch_w    = (const float*)d_in[6];
    const float* fch_b    = (const float*)d_in[7];
    const float* roll_wih = (const float*)d_in[8];
    const float* roll_whh = (const float*)d_in[9];
    const float* roll_bih = (const float*)d_in[10];
    const float* roll_bhh = (const float*)d_in[11];
    const float* u_wih    = (const float*)d_in[12];
    const float* u_whh    = (const float*)d_in[13];
    const float* u_bih    = (const float*)d_in[14];
    const float* u_bhh    = (const float*)d_in[15];
    const float* cls_w    = (const float*)d_in[16];
    const float* cls_b    = (const float*)d_in[17];
    float* out = (float*)d_out;

    cudaFuncSetAttribute(gemm_bf<0, 1>, cudaFuncAttributeMaxDynamicSharedMemorySize, GSM);
    cudaFuncSetAttribute(gemm_bf<1, 0>, cudaFuncAttributeMaxDynamicSharedMemorySize, GSM);
    cudaFuncSetAttribute(gemm_bf<0, 0>, cudaFuncAttributeMaxDynamicSharedMemorySize, GSM);
    cudaFuncSetAttribute(lstm_persistent, cudaFuncAttributeMaxDynamicSharedMemorySize, PSM);

    static cudaStream_t s1 = nullptr;
    static cudaEvent_t evFork = nullptr, evS1 = nullptr, evB = nullptr,
                       evC = nullptr, evD = nullptr;
    if (!s1) {
        cudaStreamCreateWithFlags(&s1, cudaStreamNonBlocking);
        cudaEventCreateWithFlags(&evFork, cudaEventDisableTiming);
        cudaEventCreateWithFlags(&evS1,   cudaEventDisableTiming);
        cudaEventCreateWithFlags(&evB,    cudaEventDisableTiming);
        cudaEventCreateWithFlags(&evC,    cudaEventDisableTiming);
        cudaEventCreateWithFlags(&evD,    cudaEventDisableTiming);
    }

    float* sc = nullptr;
    cudaGetSymbolAddress((void**)&sc, g_scratch);

    bf16* featsH = (bf16*)(sc + OFF_FEATSH); bf16* featsM = (bf16*)(sc + OFF_FEATSM);
    bf16* xH     = (bf16*)(sc + OFF_XH);     bf16* xM     = (bf16*)(sc + OFF_XM);
    float* gatesx  = sc + OFF_GATESX;
    float* gatesxu = sc + OFF_GATESXU;
    bf16* h0H = (bf16*)(sc + OFF_H0H); bf16* h0M = (bf16*)(sc + OFF_H0M);
    bf16* h1H = (bf16*)(sc + OFF_H1H); bf16* h1M = (bf16*)(sc + OFF_H1M);
    bf16* handsH = (bf16*)(sc + OFF_HANDSH); bf16* handsM = (bf16*)(sc + OFF_HANDSM);
    bf16* fc1H   = (bf16*)(sc + OFF_FC1H);   bf16* fc1M   = (bf16*)(sc + OFF_FC1M);
    bf16* fchwH  = (bf16*)(sc + OFF_FCHWH);  bf16* fchwM  = (bf16*)(sc + OFF_FCHWM);
    bf16* rwihH  = (bf16*)(sc + OFF_RWIHH);  bf16* rwihM  = (bf16*)(sc + OFF_RWIHM);
    bf16* rwhhH  = (bf16*)(sc + OFF_RWHHH);  bf16* rwhhM  = (bf16*)(sc + OFF_RWHHM);
    bf16* uwihH  = (bf16*)(sc + OFF_UWIHH);  bf16* uwihM  = (bf16*)(sc + OFF_UWIHM);
    bf16* uwhhH  = (bf16*)(sc + OFF_UWHHH);  bf16* uwhhM  = (bf16*)(sc + OFF_UWHHM);
    bf16* clsH   = (bf16*)(sc + OFF_CLSH);   bf16* clsM   = (bf16*)(sc + OFF_CLSM);
    float* lossrow = sc + OFF_LOSSROW;

    // ---- fork side stream ----
    cudaEventRecord(evFork, 0);
    cudaStreamWaitEvent(s1, evFork, 0);

    // side: early preps -> hproj -> evS1 ; late preps (overlap gates)
    prep_early<<<296, 256, 0, s1>>>(roll_wih, lh, rh, fch_w,
                                    rwihH, rwihM, handsH, handsM, fchwH, fchwM);
    gemm_bf<0,1><<<dim3(8,16), 256, GSM, s1>>>(handsH, handsM, HPAD,
                                               fchwH, fchwM, HPAD,
                                               nullptr, xH + HH, xM + HH, 2*HH,
                                               fch_b, nullptr, HH, HPAD);
    cudaEventRecord(evS1, s1);
    prep_late<<<296, 256, 0, s1>>>(u_wih, roll_whh, u_whh,
                                   uwihH, uwihM, rwhhH, rwhhM, uwhhH, uwhhM);

    // main: critical path
    prep_main<<<296, 256>>>(feats, fc1_w, featsH, featsM, fc1H, fc1M);
    gemm_bf<0,1><<<dim3(8,16), 256, GSM>>>(featsH, featsM, FEATD,
                                           fc1H, fc1M, FEATD,
                                           nullptr, xH, xM, 2*HH,
                                           fc1_b, nullptr, HH, FEATD);
    cudaEventRecord(evB, 0);             // xproj done
    cudaStreamWaitEvent(s1, evB, 0);     // side: gatesxu needs full x row S-1

    // side: gatesxu (overlaps the gates GEMM), then cls split (overlaps persistent)
    gemm_bf<1,0><<<dim3(32,1), 256, GSM, s1>>>(xH + (size_t)(SS-1)*BB*2*HH,
                                               xM + (size_t)(SS-1)*BB*2*HH, 2*HH,
                                               uwihH, uwihM, 2*HH,
                                               gatesxu, nullptr, nullptr, 4*HH,
                                               u_bih, u_bhh, 4*HH, 2*HH);
    cudaEventRecord(evC, s1);
    cls_split_bf<<<(1024*(HH/4) + 255)/256, 256, 0, s1>>>(cls_w, clsH, clsM);
    cudaEventRecord(evD, s1);

    // main: gates GEMM (needs hproj + rwih)
    cudaStreamWaitEvent(0, evS1, 0);
    gemm_bf<1,0><<<dim3(32,16), 256, GSM>>>(xH, xM, 2*HH,
                                            rwihH, rwihM, 2*HH,
                                            gatesx, nullptr, nullptr, 4*HH,
                                            roll_bih, roll_bhh, 4*HH, 2*HH);

    // join (gatesxu + rwhh/uwhh) before recurrence
    cudaStreamWaitEvent(0, evC, 0);

    // ---- recurrence: one persistent kernel, 18 steps ----
    lstm_persistent<<<128, PTHREADS, PSM>>>(rwhhH, rwhhM, uwhhH, uwhhM,
                                            gatesx, gatesxu,
                                            h0H, h0M, h1H, h1M);

    // classifier (needs cls split)
    cudaStreamWaitEvent(0, evD, 0);
    gemm_bf<0,0><<<dim3(8,1), 256, GSM>>>(h0H, h0M, HH,
                                          clsH, clsM, HH,
                                          out, nullptr, nullptr, CC,
                                          cls_b, nullptr, CC, HH);

    // stats
    float* pred_f = (out_size >= BB * CC + BB)     ? out + BB * CC : nullptr;
    float* loss_p = (out_size >= BB * CC + BB + 1) ? out + BB * CC + BB : nullptr;
    row_stats<<<BB, 128>>>(out, act, pred_f, lossrow);
    if (loss_p) mean_loss<<<1, 128>>>(lossrow, loss_p);
}

// round 17
// speedup vs baseline: 1.0806x; 1.0408x over previous
#include <cuda_runtime.h>
#include <cuda_bf16.h>
#include <math.h>
#include <stdint.h>

#define SS    16
#define BB    128
#define FEATD 2048
#define HANDD 63
#define HH    1024
#define CC    1000
#define HPAD  128

// ---------------------------------------------------------------------------
// Scratch layout
// ---------------------------------------------------------------------------
#define NB_FEATS (SS*BB*FEATD)
#define NB_X     (SS*BB*2*HH)
#define NB_HANDS (SS*BB*HPAD)
#define NB_FC1   (HH*FEATD)
#define NB_FCHW  (HH*HPAD)
#define NB_RWIH  (4*HH*2*HH)
#define NB_RWHH  (4*HH*HH)
#define NB_CLS   (1024*HH)
#define NB_H     (BB*HH)

#define OFF_FEATSH  0
#define OFF_FEATSM  (OFF_FEATSH + NB_FEATS/2)
#define OFF_XH      (OFF_FEATSM + NB_FEATS/2)
#define OFF_XM      (OFF_XH     + NB_X/2)
#define OFF_GATESX  (OFF_XM     + NB_X/2)
#define OFF_GATESXU (OFF_GATESX + SS*BB*4*HH)
#define OFF_H0H     (OFF_GATESXU+ BB*4*HH)
#define OFF_H0M     (OFF_H0H    + NB_H/2)
#define OFF_H1H     (OFF_H0M    + NB_H/2)
#define OFF_H1M     (OFF_H1H    + NB_H/2)
#define OFF_HANDSH  (OFF_H1M    + NB_H/2)
#define OFF_HANDSM  (OFF_HANDSH + NB_HANDS/2)
#define OFF_FC1H    (OFF_HANDSM + NB_HANDS/2)
#define OFF_FC1M    (OFF_FC1H   + NB_FC1/2)
#define OFF_FCHWH   (OFF_FC1M   + NB_FC1/2)
#define OFF_FCHWM   (OFF_FCHWH  + NB_FCHW/2)
#define OFF_RWIHH   (OFF_FCHWM  + NB_FCHW/2)
#define OFF_RWIHM   (OFF_RWIHH  + NB_RWIH/2)
#define OFF_RWHHH   (OFF_RWIHM  + NB_RWIH/2)
#define OFF_RWHHM   (OFF_RWHHH  + NB_RWHH/2)
#define OFF_UWIHH   (OFF_RWHHM  + NB_RWHH/2)
#define OFF_UWIHM   (OFF_UWIHH  + NB_RWIH/2)
#define OFF_UWHHH   (OFF_UWIHM  + NB_RWIH/2)
#define OFF_UWHHM   (OFF_UWHHH  + NB_RWHH/2)
#define OFF_CLSH    (OFF_UWHHM  + NB_RWHH/2)
#define OFF_CLSM    (OFF_CLSH   + NB_CLS/2)
#define OFF_LOSSROW (OFF_CLSM   + NB_CLS/2)
#define SCRATCH_TOT (OFF_LOSSROW + BB)

__device__ __align__(16) float g_scratch[SCRATCH_TOT];

// tree grid-barrier state (monotone counters; snapshot at entry -> replay-safe)
__device__ unsigned int g_grp[8];
__device__ unsigned int g_root  = 0;
__device__ unsigned int g_phase = 0;

typedef __nv_bfloat16 bf16;

// ---------------------------------------------------------------------------
// helpers
// ---------------------------------------------------------------------------
__device__ __forceinline__ void split_bf(float v, bf16& h, bf16& m)
{
    h = __float2bfloat16_rn(v);
    m = __float2bfloat16_rn(v - __bfloat162float(h));
}

#define MMA_BF16(d, a, b)                                                     \
    asm volatile(                                                             \
        "mma.sync.aligned.m16n8k16.row.col.f32.bf16.bf16.f32 "                \
        "{%0,%1,%2,%3},{%4,%5,%6,%7},{%8,%9},{%0,%1,%2,%3};"                  \
        : "+f"(d[0]), "+f"(d[1]), "+f"(d[2]), "+f"(d[3])                      \
        : "r"(a[0]), "r"(a[1]), "r"(a[2]), "r"(a[3]), "r"(b[0]), "r"(b[1]))

__device__ __forceinline__ void ldsm4(uint32_t& r0, uint32_t& r1,
                                      uint32_t& r2, uint32_t& r3, uint32_t addr)
{
    asm volatile("ldmatrix.sync.aligned.m8n8.x4.shared.b16 {%0,%1,%2,%3}, [%4];"
                 : "=r"(r0), "=r"(r1), "=r"(r2), "=r"(r3) : "r"(addr));
}
__device__ __forceinline__ void ldsm2(uint32_t& r0, uint32_t& r1, uint32_t addr)
{
    asm volatile("ldmatrix.sync.aligned.m8n8.x2.shared.b16 {%0,%1}, [%2];"
                 : "=r"(r0), "=r"(r1) : "r"(addr));
}

__device__ __forceinline__ void cp16(uint32_t dst, const void* src)
{
    asm volatile("cp.async.cg.shared.global [%0], [%1], 16;" :: "r"(dst), "l"(src));
}
__device__ __forceinline__ void cp_commit() { asm volatile("cp.async.commit_group;"); }
__device__ __forceinline__ void cp_wait()   { asm volatile("cp.async.wait_group 0;"); }
__device__ __forceinline__ void cp_wait1()  { asm volatile("cp.async.wait_group 1;"); }

__device__ __forceinline__ unsigned int atom_add_acqrel(unsigned int* p, unsigned int v)
{
    unsigned int old;
    asm volatile("atom.acq_rel.gpu.global.add.u32 %0, [%1], %2;"
                 : "=r"(old) : "l"(p), "r"(v) : "memory");
    return old;
}
__device__ __forceinline__ unsigned int ld_acquire(unsigned int* p)
{
    unsigned int v;
    asm volatile("ld.acquire.gpu.global.u32 %0, [%1];" : "=r"(v) : "l"(p) : "memory");
    return v;
}

// ---------------------------------------------------------------------------
// bf16x2-split GEMM (3 products): C = A*W^T (+bias)
// STAGES=2: proven 2-buffer version (2 CTAs/SM). STAGES=3: 3-buffer ring
// (2 K-tiles in flight) for single-wave latency-bound launches (xproj).
// ---------------------------------------------------------------------------
template<int PERMBIAS, int SPLITOUT, int STAGES>
__global__ void __launch_bounds__(256, 2)
gemm_bf(const bf16* __restrict__ AH, const bf16* __restrict__ AM, int lda,
        const bf16* __restrict__ WH, const bf16* __restrict__ WM, int ldw,
        float* __restrict__ Cf, bf16* __restrict__ CbH, bf16* __restrict__ CbM,
        int ldc, const float* __restrict__ b1, const float* __restrict__ b2,
        int Nstore, int K)
{
    extern __shared__ __align__(16) char smraw[];
    const uint32_t sbase = (uint32_t)__cvta_generic_to_shared(smraw);

    const int tid  = threadIdx.x;
    const int lane = tid & 31;
    const int warp = tid >> 5;
    const int wm   = warp >> 2;
    const int wn   = warp & 3;
    const int row0 = blockIdx.y * 128;
    const int col0 = blockIdx.x * 128;

    float acc[4][4][4];
#pragma unroll
    for (int i = 0; i < 4; i++)
#pragma unroll
        for (int j = 0; j < 4; j++)
#pragma unroll
            for (int q = 0; q < 4; q++) acc[i][j][q] = 0.f;

    const int r  = tid >> 2;
    const int ch = tid & 3;

    auto gload = [&](int buf, int k0) {
        const uint32_t bo = (uint32_t)(buf * 40960);
#pragma unroll
        for (int l = 0; l < 2; l++) {
            int rr = r + l * 64;
            uint32_t so = (uint32_t)(rr * 80 + ch * 16);
            cp16(sbase + bo +         so, &AH[(size_t)(row0 + rr) * lda + k0 + ch * 8]);
            cp16(sbase + bo + 10240 + so, &AM[(size_t)(row0 + rr) * lda + k0 + ch * 8]);
            cp16(sbase + bo + 20480 + so, &WH[(size_t)(col0 + rr) * ldw + k0 + ch * 8]);
            cp16(sbase + bo + 30720 + so, &WM[(size_t)(col0 + rr) * ldw + k0 + ch * 8]);
        }
        cp_commit();
    };

    auto compute = [&](int buf) {
        const uint32_t bo  = (uint32_t)(buf * 40960);
        const uint32_t aA0 = sbase + bo;
        const uint32_t aA1 = sbase + bo + 10240;
        const uint32_t aB0 = sbase + bo + 20480;
        const uint32_t aB1 = sbase + bo + 30720;

#pragma unroll
        for (int s = 0; s < 2; s++) {
            uint32_t b0f[4][2], b1f[4][2];
            const uint32_t bOff = (uint32_t)((lane & 7) * 80 + s * 32 + ((lane >> 3) & 1) * 16);
#pragma unroll
            for (int nt = 0; nt < 4; nt++) {
                uint32_t na = (uint32_t)((wn * 32 + nt * 8) * 80);
                ldsm2(b0f[nt][0], b0f[nt][1], aB0 + na + bOff);
                ldsm2(b1f[nt][0], b1f[nt][1], aB1 + na + bOff);
            }
            const uint32_t aOff = (uint32_t)((lane & 15) * 80 + s * 32 + (lane >> 4) * 16);
#pragma unroll
            for (int mt = 0; mt < 4; mt++) {
                uint32_t ma = (uint32_t)((wm * 64 + mt * 16) * 80);
                uint32_t a0[4], a1[4];
                ldsm4(a0[0], a0[1], a0[2], a0[3], aA0 + ma + aOff);
                ldsm4(a1[0], a1[1], a1[2], a1[3], aA1 + ma + aOff);
#pragma unroll
                for (int nt = 0; nt < 4; nt++) {
                    MMA_BF16(acc[mt][nt], a0, b0f[nt]);
                    MMA_BF16(acc[mt][nt], a0, b1f[nt]);
                    MMA_BF16(acc[mt][nt], a1, b0f[nt]);
                }
            }
        }
    };

    const int nk = K / 32;

    if (STAGES == 2) {
        gload(0, 0);
        cp_wait();
        __syncthreads();
        for (int kt = 0; kt < nk; kt++) {
            const int cur = kt & 1;
            if (kt + 1 < nk) gload(cur ^ 1, (kt + 1) * 32);
            compute(cur);
            if (kt + 1 < nk) { cp_wait(); __syncthreads(); }
        }
    } else {
        gload(0, 0);
        if (nk > 1) gload(1, 32);
        for (int kt = 0; kt < nk; kt++) {
            if (kt + 1 < nk) cp_wait1(); else cp_wait();   // buffer kt ready
            __syncthreads();                               // prev compute drained
            if (kt + 2 < nk) gload((kt + 2) % 3, (kt + 2) * 32);
            compute(kt % 3);
        }
    }

#pragma unroll
    for (int mt = 0; mt < 4; mt++)
#pragma unroll
        for (int nt = 0; nt < 4; nt++) {
            int m = row0 + wm * 64 + mt * 16 + (lane >> 2);
            int n = col0 + wn * 32 + nt * 8 + 2 * (lane & 3);
            if (n + 1 >= Nstore) continue;
            float bv0 = 0.f, bv1 = 0.f;
            int bi0 = PERMBIAS ? ((n & 3) * HH + (n >> 2)) : n;
            int bi1 = PERMBIAS ? (((n + 1) & 3) * HH + ((n + 1) >> 2)) : (n + 1);
            if (b1) { bv0 += b1[bi0]; bv1 += b1[bi1]; }
            if (b2) { bv0 += b2[bi0]; bv1 += b2[bi1]; }
            float v00 = acc[mt][nt][0] + bv0, v01 = acc[mt][nt][1] + bv1;
            float v10 = acc[mt][nt][2] + bv0, v11 = acc[mt][nt][3] + bv1;
            if (SPLITOUT) {
                __nv_bfloat162 h0, m0, h1, m1;
                split_bf(v00, h0.x, m0.x); split_bf(v01, h0.y, m0.y);
                split_bf(v10, h1.x, m1.x); split_bf(v11, h1.y, m1.y);
                *reinterpret_cast<__nv_bfloat162*>(&CbH[(size_t)m * ldc + n])       = h0;
                *reinterpret_cast<__nv_bfloat162*>(&CbM[(size_t)m * ldc + n])       = m0;
                *reinterpret_cast<__nv_bfloat162*>(&CbH[(size_t)(m + 8) * ldc + n]) = h1;
                *reinterpret_cast<__nv_bfloat162*>(&CbM[(size_t)(m + 8) * ldc + n]) = m1;
            } else {
                *reinterpret_cast<float2*>(&Cf[(size_t)m * ldc + n])       = make_float2(v00, v01);
                *reinterpret_cast<float2*>(&Cf[(size_t)(m + 8) * ldc + n]) = make_float2(v10, v11);
            }
        }
}

// ---------------------------------------------------------------------------
// Persistent LSTM recurrence — R13 proven version (unchanged).
// ---------------------------------------------------------------------------
#define PSM  228352
#define ABUF 36864
#define ASTR 144
#define SW_H 73728
#define SW_M 140800
#define SGX  207872
#define SCC  224256
#define WSTR 2096
#define PTHREADS 512

__global__ void __launch_bounds__(PTHREADS)
lstm_persistent(const bf16* __restrict__ rwhhH, const bf16* __restrict__ rwhhM,
                const bf16* __restrict__ uwhhH, const bf16* __restrict__ uwhhM,
                const float* __restrict__ gatesx,
                const float* __restrict__ gatesxu,
                bf16* __restrict__ h0H, bf16* __restrict__ h0M,
                bf16* __restrict__ h1H, bf16* __restrict__ h1M)
{
    extern __shared__ __align__(16) char smraw[];
    const uint32_t sbase = (uint32_t)__cvta_generic_to_shared(smraw);
    float* gsum = reinterpret_cast<float*>(smraw);
    float* c_sm = reinterpret_cast<float*>(smraw + SCC);

    const int tid  = threadIdx.x;
    const int lane = tid & 31;
    const int warp = tid >> 5;
    const int wm   = warp >> 1;
    const int wn   = warp & 1;
    const int col0 = blockIdx.x * 32;
    const int grp  = blockIdx.x >> 4;

    __shared__ unsigned int s_phase;
    if (tid == 0) s_phase = g_phase;

#pragma unroll
    for (int q = 0; q < 2; q++) c_sm[tid + q * PTHREADS] = 0.f;

    auto load_weights = [&](const bf16* wH, const bf16* wM) {
        for (int i = tid; i < 4096; i += PTHREADS) {
            int row = i >> 7;
            int chk = i & 127;
            uint32_t so = (uint32_t)(row * WSTR + chk * 16);
            cp16(sbase + SW_H + so, &wH[(size_t)(col0 + row) * HH + chk * 8]);
            cp16(sbase + SW_M + so, &wM[(size_t)(col0 + row) * HH + chk * 8]);
        }
        cp_commit();
        cp_wait();
        __syncthreads();
    };
    load_weights(rwhhH, rwhhM);

    for (int step = 0; step < 18; step++) {
        const bf16* hH = (step & 1) ? h1H : h0H;
        const bf16* hM = (step & 1) ? h1M : h0M;
        bf16* oH = (step & 1) ? h0H : h1H;
        bf16* oM = (step & 1) ? h0M : h1M;
        const float* gx = (step < SS) ? gatesx + (size_t)step * BB * 4 * HH
                                      : gatesxu;

        if (step == SS) load_weights(uwhhH, uwhhM);

        {
#pragma unroll
            for (int l = 0; l < 2; l++) {
                int idx = tid + l * PTHREADS;
                int b   = idx >> 3;
                int chk = idx & 7;
                cp16(sbase + SGX + (uint32_t)(b * 128 + chk * 16),
                     &gx[(size_t)b * (4 * HH) + col0 + chk * 4]);
            }
            cp_commit();
        }

        float acc[2][4];
#pragma unroll
        for (int j = 0; j < 2; j++)
#pragma unroll
            for (int q = 0; q < 4; q++) acc[j][q] = 0.f;

        if (step > 0) {
            auto gloadA = [&](int buf, int k0) {
                const uint32_t bo = (uint32_t)(buf * ABUF);
#pragma unroll
                for (int l = 0; l < 2; l++) {
                    int idx = tid + l * PTHREADS;
                    int row = idx >> 3;
                    int chk = idx & 7;
                    uint32_t so = (uint32_t)(row * ASTR + chk * 16);
                    cp16(sbase + bo +         so, &hH[(size_t)row * HH + k0 + chk * 8]);
                    cp16(sbase + bo + 18432 + so, &hM[(size_t)row * HH + k0 + chk * 8]);
                }
                cp_commit();
            };

            gloadA(0, 0);

            for (int kt = 0; kt < 16; kt++) {
                if (kt + 1 < 16) { gloadA((kt + 1) & 1, (kt + 1) * 64); cp_wait1(); }
                else             { cp_wait(); }
                __syncthreads();

                const uint32_t aA0 = sbase + (uint32_t)((kt & 1) * ABUF);
                const uint32_t aA1 = aA0 + 18432;

#pragma unroll
                for (int s = 0; s < 4; s++) {
                    uint32_t b0f[2][2], b1f[2][2];
                    const uint32_t bOff = (uint32_t)((lane & 7) * WSTR + kt * 128
                                                     + s * 32 + ((lane >> 3) & 1) * 16);
#pragma unroll
                    for (int nt = 0; nt < 2; nt++) {
                        uint32_t na = (uint32_t)((wn * 16 + nt * 8) * WSTR);
                        ldsm2(b0f[nt][0], b0f[nt][1], sbase + SW_H + na + bOff);
                        ldsm2(b1f[nt][0], b1f[nt][1], sbase + SW_M + na + bOff);
                    }
                    const uint32_t aOff = (uint32_t)((wm * 16 + (lane & 15)) * ASTR
                                                     + s * 32 + (lane >> 4) * 16);
                    uint32_t a0[4], a1[4];
                    ldsm4(a0[0], a0[1], a0[2], a0[3], aA0 + aOff);
                    ldsm4(a1[0], a1[1], a1[2], a1[3], aA1 + aOff);
#pragma unroll
                    for (int nt = 0; nt < 2; nt++) {
                        MMA_BF16(acc[nt], a0, b0f[nt]);
                        MMA_BF16(acc[nt], a0, b1f[nt]);
                        MMA_BF16(acc[nt], a1, b0f[nt]);
                    }
                }
            }
            __syncthreads();
        } else {
            cp_wait();
            __syncthreads();
        }

#pragma unroll
        for (int nt = 0; nt < 2; nt++) {
            int m = wm * 16 + (lane >> 2);
            int n = wn * 16 + nt * 8 + 2 * (lane & 3);
            gsum[m * 36 + n]           = acc[nt][0];
            gsum[m * 36 + n + 1]       = acc[nt][1];
            gsum[(m + 8) * 36 + n]     = acc[nt][2];
            gsum[(m + 8) * 36 + n + 1] = acc[nt][3];
        }
        __syncthreads();

#pragma unroll
        for (int q = 0; q < 2; q++) {
            int idx = tid + q * PTHREADS;
            int b  = idx >> 3;
            int jj = idx & 7;
            float4 g  = *reinterpret_cast<float4*>(&gsum[b * 36 + jj * 4]);
            float4 gv = *reinterpret_cast<float4*>(smraw + SGX + b * 128 + jj * 16);
            float gi = g.x + gv.x;
            float gf = g.y + gv.y;
            float gg = g.z + gv.z;
            float go = g.w + gv.w;
            float si = 1.f / (1.f + expf(-gi));
            float sf = 1.f / (1.f + expf(-gf));
            float so = 1.f / (1.f + expf(-go));
            float tg = tanhf(gg);
            float cn = sf * c_sm[b * 8 + jj] + si * tg;
            float hn = so * tanhf(cn);
            c_sm[b * 8 + jj] = cn;
            int j = (col0 >> 2) + jj;
            bf16 hh, hm;
            split_bf(hn, hh, hm);
            oH[(size_t)b * HH + j] = hh;
            oM[(size_t)b * HH + j] = hm;
        }

        if (step < 17) {
            __syncthreads();
            if (tid == 0) {
                const unsigned int R = s_phase + (unsigned int)step;
                unsigned int t1 = atom_add_acqrel(&g_grp[grp], 1);
                if (t1 == R * 16 + 15) {
                    unsigned int t2 = atom_add_acqrel(&g_root, 1);
                    if (t2 == R * 8 + 7) atom_add_acqrel(&g_phase, 1);
                }
                while (ld_acquire(&g_phase) <= R) { }
            }
            __syncthreads();
        }
    }
}

// ---------------------------------------------------------------------------
// Prep kernels (fp32 -> split bf16), grid-stride
// ---------------------------------------------------------------------------
__global__ void prep_main(const float* __restrict__ feats,
                          const float* __restrict__ fc1_w,
                          bf16* __restrict__ featsH, bf16* __restrict__ featsM,
                          bf16* __restrict__ fc1H,   bf16* __restrict__ fc1M)
{
    const int stride = gridDim.x * blockDim.x;
    int g = blockIdx.x * blockDim.x + threadIdx.x;
    for (int i = g; i < NB_FEATS / 4; i += stride) {
        float4 v = reinterpret_cast<const float4*>(feats)[i];
        __nv_bfloat162 h0, h1, m0, m1;
        split_bf(v.x, h0.x, m0.x); split_bf(v.y, h0.y, m0.y);
        split_bf(v.z, h1.x, m1.x); split_bf(v.w, h1.y, m1.y);
        reinterpret_cast<__nv_bfloat162*>(featsH)[2 * i]     = h0;
        reinterpret_cast<__nv_bfloat162*>(featsH)[2 * i + 1] = h1;
        reinterpret_cast<__nv_bfloat162*>(featsM)[2 * i]     = m0;
        reinterpret_cast<__nv_bfloat162*>(featsM)[2 * i + 1] = m1;
    }
    for (int i = g; i < NB_FC1 / 4; i += stride) {
        float4 v = reinterpret_cast<const float4*>(fc1_w)[i];
        __nv_bfloat162 h0, h1, m0, m1;
        split_bf(v.x, h0.x, m0.x); split_bf(v.y, h0.y, m0.y);
        split_bf(v.z, h1.x, m1.x); split_bf(v.w, h1.y, m1.y);
        reinterpret_cast<__nv_bfloat162*>(fc1H)[2 * i]     = h0;
        reinterpret_cast<__nv_bfloat162*>(fc1H)[2 * i + 1] = h1;
        reinterpret_cast<__nv_bfloat162*>(fc1M)[2 * i]     = m0;
        reinterpret_cast<__nv_bfloat162*>(fc1M)[2 * i + 1] = m1;
    }
}

__device__ __forceinline__ void perm_split_body(const float* s, bf16* H, bf16* M,
                                                int cols, int i)
{
    int cols4 = cols >> 2;
    int p  = i / cols4;
    int cq = i % cols4;
    int sr = (p & 3) * HH + (p >> 2);
    float4 v = *reinterpret_cast<const float4*>(&s[(size_t)sr * cols + cq * 4]);
    __nv_bfloat162 h0, h1, m0, m1;
    split_bf(v.x, h0.x, m0.x); split_bf(v.y, h0.y, m0.y);
    split_bf(v.z, h1.x, m1.x); split_bf(v.w, h1.y, m1.y);
    size_t o = (size_t)p * cols + cq * 4;
    *reinterpret_cast<__nv_bfloat162*>(&H[o])     = h0;
    *reinterpret_cast<__nv_bfloat162*>(&H[o + 2]) = h1;
    *reinterpret_cast<__nv_bfloat162*>(&M[o])     = m0;
    *reinterpret_cast<__nv_bfloat162*>(&M[o + 2]) = m1;
}

__global__ void prep_early(const float* __restrict__ roll_wih,
                           const float* __restrict__ lh,
                           const float* __restrict__ rh,
                           const float* __restrict__ fch_w,
                           bf16* rwihH, bf16* rwihM,
                           bf16* handsH, bf16* handsM,
                           bf16* fchwH, bf16* fchwM)
{
    const int stride = gridDim.x * blockDim.x;
    int g = blockIdx.x * blockDim.x + threadIdx.x;
    const int N_IH = 4 * HH * (2 * HH / 4);
    for (int i = g; i < N_IH; i += stride) perm_split_body(roll_wih, rwihH, rwihM, 2*HH, i);
    for (int i = g; i < SS * BB * HPAD; i += stride) {
        int col = i % HPAD, row = i / HPAD;
        float v = 0.f;
        if (col < HANDD)          v = lh[row * HANDD + col];
        else if (col < 2 * HANDD) v = rh[row * HANDD + (col - HANDD)];
        bf16 h, m; split_bf(v, h, m);
        handsH[i] = h; handsM[i] = m;
    }
    for (int i = g; i < HH * HPAD; i += stride) {
        int col = i % HPAD, row = i / HPAD;
        float v = (col < 2 * HANDD) ? fch_w[row * 2 * HANDD + col] : 0.f;
        bf16 h, m; split_bf(v, h, m);
        fchwH[i] = h; fchwM[i] = m;
    }
}

__global__ void prep_late(const float* __restrict__ u_wih,
                          const float* __restrict__ roll_whh,
                          const float* __restrict__ u_whh,
                          bf16* uwihH, bf16* uwihM,
                          bf16* rwhhH, bf16* rwhhM, bf16* uwhhH, bf16* uwhhM)
{
    const int stride = gridDim.x * blockDim.x;
    int g = blockIdx.x * blockDim.x + threadIdx.x;
    const int N_IH = 4 * HH * (2 * HH / 4);
    const int N_HH = 4 * HH * (HH / 4);
    for (int i = g; i < N_IH; i += stride) perm_split_body(u_wih,    uwihH, uwihM, 2*HH, i);
    for (int i = g; i < N_HH; i += stride) perm_split_body(roll_whh, rwhhH, rwhhM, HH, i);
    for (int i = g; i < N_HH; i += stride) perm_split_body(u_whh,    uwhhH, uwhhM, HH, i);
}

__global__ void cls_split_bf(const float* __restrict__ w,
                             bf16* __restrict__ H, bf16* __restrict__ M)
{
    int i = blockIdx.x * blockDim.x + threadIdx.x;
    if (i >= 1024 * (HH / 4)) return;
    int rr = i / (HH / 4), cq = i % (HH / 4);
    float4 v = (rr < CC)
        ? *reinterpret_cast<const float4*>(&w[(size_t)rr * HH + cq * 4])
        : make_float4(0.f, 0.f, 0.f, 0.f);
    __nv_bfloat162 h0, h1, m0, m1;
    split_bf(v.x, h0.x, m0.x); split_bf(v.y, h0.y, m0.y);
    split_bf(v.z, h1.x, m1.x); split_bf(v.w, h1.y, m1.y);
    size_t o = (size_t)rr * HH + cq * 4;
    *reinterpret_cast<__nv_bfloat162*>(&H[o])     = h0;
    *reinterpret_cast<__nv_bfloat162*>(&H[o + 2]) = h1;
    *reinterpret_cast<__nv_bfloat162*>(&M[o])     = m0;
    *reinterpret_cast<__nv_bfloat162*>(&M[o + 2]) = m1;
}

__global__ void row_stats(const float* __restrict__ out,
                          const int* __restrict__ act,
                          float* __restrict__ pred_f,
                          float* __restrict__ lossrow)
{
    const int b = blockIdx.x;
    const float* row = out + (size_t)b * CC;
    __shared__ float smax[128];
    __shared__ int   sidx[128];
    __shared__ float ssum[128];
    const int t = threadIdx.x;

    float best = -INFINITY;
    int bidx = 0;
    for (int j = t; j < CC; j += 128) {
        float v = row[j];
        if (v > best) { best = v; bidx = j; }
    }
    smax[t] = best; sidx[t] = bidx;
    __syncthreads();
    for (int s = 64; s > 0; s >>= 1) {
        if (t < s) {
            float v2 = smax[t + s]; int i2 = sidx[t + s];
            if (v2 > smax[t] || (v2 == smax[t] && i2 < sidx[t])) {
                smax[t] = v2; sidx[t] = i2;
            }
        }
        __syncthreads();
    }
    const float rowmax = smax[0];
    const int   rowarg = sidx[0];

    float lsum = 0.f;
    for (int j = t; j < CC; j += 128) lsum += expf(row[j] - rowmax);
    ssum[t] = lsum;
    __syncthreads();
    for (int s = 64; s > 0; s >>= 1) {
        if (t < s) ssum[t] += ssum[t + s];
        __syncthreads();
    }
    if (t == 0) {
        float logz = rowmax + logf(ssum[0]);
        lossrow[b] = logz - row[act[b]];
        if (pred_f) pred_f[b] = (float)rowarg;
    }
}

__global__ void mean_loss(const float* __restrict__ lossrow, float* loss_out)
{
    __shared__ float s[128];
    int t = threadIdx.x;
    s[t] = lossrow[t];
    __syncthreads();
    for (int st = 64; st > 0; st >>= 1) {
        if (t < st) s[t] += s[t + st];
        __syncthreads();
    }
    if (t == 0) *loss_out = s[0] / (float)BB;
}

// ---------------------------------------------------------------------------
// Launch — prep_late now gated on xproj completion so its DRAM traffic
// overlaps the long gates GEMM instead of the latency-bound xproj.
// ---------------------------------------------------------------------------
#define GSM  81920
#define GSM3 122880

extern "C" void kernel_launch(void* const* d_in, const int* in_sizes, int n_in,
                              void* d_out, int out_size)
{
    const float* feats    = (const float*)d_in[0];
    const float* lh       = (const float*)d_in[1];
    const float* rh       = (const float*)d_in[2];
    const int*   act      = (const int*)  d_in[3];
    const float* fc1_w    = (const float*)d_in[4];
    const float* fc1_b    = (const float*)d_in[5];
    const float* fch_w    = (const float*)d_in[6];
    const float* fch_b    = (const float*)d_in[7];
    const float* roll_wih = (const float*)d_in[8];
    const float* roll_whh = (const float*)d_in[9];
    const float* roll_bih = (const float*)d_in[10];
    const float* roll_bhh = (const float*)d_in[11];
    const float* u_wih    = (const float*)d_in[12];
    const float* u_whh    = (const float*)d_in[13];
    const float* u_bih    = (const float*)d_in[14];
    const float* u_bhh    = (const float*)d_in[15];
    const float* cls_w    = (const float*)d_in[16];
    const float* cls_b    = (const float*)d_in[17];
    float* out = (float*)d_out;

    cudaFuncSetAttribute(gemm_bf<0, 1, 2>, cudaFuncAttributeMaxDynamicSharedMemorySize, GSM);
    cudaFuncSetAttribute(gemm_bf<0, 1, 3>, cudaFuncAttributeMaxDynamicSharedMemorySize, GSM3);
    cudaFuncSetAttribute(gemm_bf<1, 0, 2>, cudaFuncAttributeMaxDynamicSharedMemorySize, GSM);
    cudaFuncSetAttribute(gemm_bf<0, 0, 2>, cudaFuncAttributeMaxDynamicSharedMemorySize, GSM);
    cudaFuncSetAttribute(lstm_persistent, cudaFuncAttributeMaxDynamicSharedMemorySize, PSM);

    static cudaStream_t s1 = nullptr;
    static cudaEvent_t evFork = nullptr, evS1 = nullptr, evB = nullptr,
                       evC = nullptr, evD = nullptr;
    if (!s1) {
        cudaStreamCreateWithFlags(&s1, cudaStreamNonBlocking);
        cudaEventCreateWithFlags(&evFork, cudaEventDisableTiming);
        cudaEventCreateWithFlags(&evS1,   cudaEventDisableTiming);
        cudaEventCreateWithFlags(&evB,    cudaEventDisableTiming);
        cudaEventCreateWithFlags(&evC,    cudaEventDisableTiming);
        cudaEventCreateWithFlags(&evD,    cudaEventDisableTiming);
    }

    float* sc = nullptr;
    cudaGetSymbolAddress((void**)&sc, g_scratch);

    bf16* featsH = (bf16*)(sc + OFF_FEATSH); bf16* featsM = (bf16*)(sc + OFF_FEATSM);
    bf16* xH     = (bf16*)(sc + OFF_XH);     bf16* xM     = (bf16*)(sc + OFF_XM);
    float* gatesx  = sc + OFF_GATESX;
    float* gatesxu = sc + OFF_GATESXU;
    bf16* h0H = (bf16*)(sc + OFF_H0H); bf16* h0M = (bf16*)(sc + OFF_H0M);
    bf16* h1H = (bf16*)(sc + OFF_H1H); bf16* h1M = (bf16*)(sc + OFF_H1M);
    bf16* handsH = (bf16*)(sc + OFF_HANDSH); bf16* handsM = (bf16*)(sc + OFF_HANDSM);
    bf16* fc1H   = (bf16*)(sc + OFF_FC1H);   bf16* fc1M   = (bf16*)(sc + OFF_FC1M);
    bf16* fchwH  = (bf16*)(sc + OFF_FCHWH);  bf16* fchwM  = (bf16*)(sc + OFF_FCHWM);
    bf16* rwihH  = (bf16*)(sc + OFF_RWIHH);  bf16* rwihM  = (bf16*)(sc + OFF_RWIHM);
    bf16* rwhhH  = (bf16*)(sc + OFF_RWHHH);  bf16* rwhhM  = (bf16*)(sc + OFF_RWHHM);
    bf16* uwihH  = (bf16*)(sc + OFF_UWIHH);  bf16* uwihM  = (bf16*)(sc + OFF_UWIHM);
    bf16* uwhhH  = (bf16*)(sc + OFF_UWHHH);  bf16* uwhhM  = (bf16*)(sc + OFF_UWHHM);
    bf16* clsH   = (bf16*)(sc + OFF_CLSH);   bf16* clsM   = (bf16*)(sc + OFF_CLSM);
    float* lossrow = sc + OFF_LOSSROW;

    // ---- fork side stream ----
    cudaEventRecord(evFork, 0);
    cudaStreamWaitEvent(s1, evFork, 0);

    // side: early preps -> hproj -> evS1
    prep_early<<<296, 256, 0, s1>>>(roll_wih, lh, rh, fch_w,
                                    rwihH, rwihM, handsH, handsM, fchwH, fchwM);
    gemm_bf<0,1,2><<<dim3(8,16), 256, GSM, s1>>>(handsH, handsM, HPAD,
                                                 fchwH, fchwM, HPAD,
                                                 nullptr, xH + HH, xM + HH, 2*HH,
                                                 fch_b, nullptr, HH, HPAD);
    cudaEventRecord(evS1, s1);

    // main: critical path — prep_main then xproj (3-stage ring, clean window)
    prep_main<<<296, 256>>>(feats, fc1_w, featsH, featsM, fc1H, fc1M);
    gemm_bf<0,1,3><<<dim3(8,16), 256, GSM3>>>(featsH, featsM, FEATD,
                                              fc1H, fc1M, FEATD,
                                              nullptr, xH, xM, 2*HH,
                                              fc1_b, nullptr, HH, FEATD);
    cudaEventRecord(evB, 0);             // xproj done

    // side: AFTER xproj — prep_late + gatesxu overlap the gates GEMM,
    // cls split overlaps the persistent kernel.
    cudaStreamWaitEvent(s1, evB, 0);
    prep_late<<<296, 256, 0, s1>>>(u_wih, roll_whh, u_whh,
                                   uwihH, uwihM, rwhhH, rwhhM, uwhhH, uwhhM);
    gemm_bf<1,0,2><<<dim3(32,1), 256, GSM, s1>>>(xH + (size_t)(SS-1)*BB*2*HH,
                                                 xM + (size_t)(SS-1)*BB*2*HH, 2*HH,
                                                 uwihH, uwihM, 2*HH,
                                                 gatesxu, nullptr, nullptr, 4*HH,
                                                 u_bih, u_bhh, 4*HH, 2*HH);
    cudaEventRecord(evC, s1);
    cls_split_bf<<<(1024*(HH/4) + 255)/256, 256, 0, s1>>>(cls_w, clsH, clsM);
    cudaEventRecord(evD, s1);

    // main: gates GEMM (needs hproj + rwih from side stream)
    cudaStreamWaitEvent(0, evS1, 0);
    gemm_bf<1,0,2><<<dim3(32,16), 256, GSM>>>(xH, xM, 2*HH,
                                              rwihH, rwihM, 2*HH,
                                              gatesx, nullptr, nullptr, 4*HH,
                                              roll_bih, roll_bhh, 4*HH, 2*HH);

    // join (prep_late + gatesxu) before recurrence
    cudaStreamWaitEvent(0, evC, 0);

    // ---- recurrence: one persistent kernel, 18 steps ----
    lstm_persistent<<<128, PTHREADS, PSM>>>(rwhhH, rwhhM, uwhhH, uwhhM,
                                            gatesx, gatesxu,
                                            h0H, h0M, h1H, h1M);

    // classifier (needs cls split)
    cudaStreamWaitEvent(0, evD, 0);
    gemm_bf<0,0,2><<<dim3(8,1), 256, GSM>>>(h0H, h0M, HH,
                                            clsH, clsM, HH,
                                            out, nullptr, nullptr, CC,
                                            cls_b, nullptr, CC, HH);

    // stats
    float* pred_f = (out_size >= BB * CC + BB)     ? out + BB * CC : nullptr;
    float* loss_p = (out_size >= BB * CC + BB + 1) ? out + BB * CC + BB : nullptr;
    row_stats<<<BB, 128>>>(out, act, pred_f, lossrow);
    if (loss_p) mean_loss<<<1, 128>>>(lossrow, loss_p);
}